// round 1
// baseline (speedup 1.0000x reference)
#include <cuda_runtime.h>
#include <cuda_bf16.h>
#include <cstdint>

// ============================================================================
// Fused SDPA with attn-matrix output.
//   scores = (q/8) @ k^T, masked (-1e9 -> exp==0), softmax, out = attn @ v
//   outputs: d_out[0 .. B*H*S*D)           = output  (fp32)
//            d_out[B*H*S*D .. +B*H*S*S)    = attn    (fp32)
//
// Design: per CTA: 128 queries x all 2048 keys, bh = blockIdx.y.
//   Phase 1: QK (3-split bf16 mma) -> exp -> rowsums.
//   Phase 2: recompute QK -> normalized p -> write attn + PV mma (P fragments
//            repacked from C registers, no smem round trip).
// Precision: 3-term bf16 split emulation (~fp32) for both GEMMs.
// ============================================================================

namespace {

constexpr int S_  = 2048;
constexpr int D_  = 64;
constexpr int BH_ = 32;          // B*H
constexpr int TQ_ = 128;         // queries per CTA
constexpr int KT_ = 64;          // keys per smem tile
constexpr int NKT_ = S_ / KT_;   // 32 key tiles
constexpr int THREADS_ = 256;    // 8 warps, warp w owns queries [16w,16w+16)
constexpr int ROWP_ = 72;        // padded bf16 row (144B, 16B aligned, LDSM conflict-free)

constexpr int SQH_OFF  = 0;
constexpr int SQL_OFF  = SQH_OFF + TQ_ * ROWP_ * 2;
constexpr int SKH_OFF  = SQL_OFF + TQ_ * ROWP_ * 2;
constexpr int SKL_OFF  = SKH_OFF + KT_ * ROWP_ * 2;
constexpr int SVH_OFF  = SKL_OFF + KT_ * ROWP_ * 2;
constexpr int SVL_OFF  = SVH_OFF + KT_ * ROWP_ * 2;
constexpr int SMASK_OFF = SVL_OFF + KT_ * ROWP_ * 2;
constexpr int SRS_OFF  = SMASK_OFF + KT_ * 4;
constexpr int SMEM_BYTES = SRS_OFF + TQ_ * 4;   // 74496 bytes

__device__ __forceinline__ uint32_t smem_u32(const void* p) {
    return (uint32_t)__cvta_generic_to_shared(p);
}

__device__ __forceinline__ void ldsm_x4(uint32_t a[4], uint32_t addr) {
    asm volatile("ldmatrix.sync.aligned.m8n8.x4.shared.b16 {%0,%1,%2,%3}, [%4];"
                 : "=r"(a[0]), "=r"(a[1]), "=r"(a[2]), "=r"(a[3]) : "r"(addr));
}
__device__ __forceinline__ void ldsm_x2(uint32_t b[2], uint32_t addr) {
    asm volatile("ldmatrix.sync.aligned.m8n8.x2.shared.b16 {%0,%1}, [%2];"
                 : "=r"(b[0]), "=r"(b[1]) : "r"(addr));
}
__device__ __forceinline__ void ldsm_x2t(uint32_t b[2], uint32_t addr) {
    asm volatile("ldmatrix.sync.aligned.m8n8.x2.trans.shared.b16 {%0,%1}, [%2];"
                 : "=r"(b[0]), "=r"(b[1]) : "r"(addr));
}
__device__ __forceinline__ void mma16816(float c[4], const uint32_t a[4], const uint32_t b[2]) {
    asm volatile(
        "mma.sync.aligned.m16n8k16.row.col.f32.bf16.bf16.f32 "
        "{%0,%1,%2,%3}, {%4,%5,%6,%7}, {%8,%9}, {%0,%1,%2,%3};"
        : "+f"(c[0]), "+f"(c[1]), "+f"(c[2]), "+f"(c[3])
        : "r"(a[0]), "r"(a[1]), "r"(a[2]), "r"(a[3]), "r"(b[0]), "r"(b[1]));
}

// Pack two fp32 into bf16x2 hi fragment + bf16x2 residual-lo fragment.
__device__ __forceinline__ void split2(float x, float y, uint32_t& hi, uint32_t& lo) {
    __nv_bfloat16 hx = __float2bfloat16(x);
    __nv_bfloat16 hy = __float2bfloat16(y);
    hi = ((uint32_t)__bfloat16_as_ushort(hy) << 16) | (uint32_t)__bfloat16_as_ushort(hx);
    __nv_bfloat16 lx = __float2bfloat16(x - __bfloat162float(hx));
    __nv_bfloat16 ly = __float2bfloat16(y - __bfloat162float(hy));
    lo = ((uint32_t)__bfloat16_as_ushort(ly) << 16) | (uint32_t)__bfloat16_as_ushort(lx);
}

// One 16x8 QK score tile: 4 d-steps x (hi*hi + hi*lo + lo*hi).
__device__ __forceinline__ void qk_tile(float c[4],
                                        const uint32_t aH[4][4], const uint32_t aL[4][4],
                                        uint32_t bah, uint32_t bal) {
#pragma unroll
    for (int ds = 0; ds < 4; ds++) {
        uint32_t bh2[2], bl2[2];
        ldsm_x2(bh2, bah + ds * 32);   // +16 bf16 along d per step
        ldsm_x2(bl2, bal + ds * 32);
        mma16816(c, aH[ds], bh2);
        mma16816(c, aH[ds], bl2);
        mma16816(c, aL[ds], bh2);
    }
}

__global__ void __launch_bounds__(THREADS_)
attn_kernel(const float* __restrict__ Q, const float* __restrict__ K,
            const float* __restrict__ V, const int* __restrict__ M,
            float* __restrict__ Out) {
    extern __shared__ char smem[];
    __nv_bfloat16* sQh = (__nv_bfloat16*)(smem + SQH_OFF);
    __nv_bfloat16* sQl = (__nv_bfloat16*)(smem + SQL_OFF);
    __nv_bfloat16* sKh = (__nv_bfloat16*)(smem + SKH_OFF);
    __nv_bfloat16* sKl = (__nv_bfloat16*)(smem + SKL_OFF);
    __nv_bfloat16* sVh = (__nv_bfloat16*)(smem + SVH_OFF);
    __nv_bfloat16* sVl = (__nv_bfloat16*)(smem + SVL_OFF);
    int*   smask = (int*)(smem + SMASK_OFF);
    float* srs   = (float*)(smem + SRS_OFF);

    const int qt = blockIdx.x;
    const int bh = blockIdx.y;
    const int tid = threadIdx.x;
    const int wid = tid >> 5;
    const int lane = tid & 31;
    const int b = bh >> 4;  // H = 16

    const size_t base = (size_t)bh * S_ * D_;
    const float* Qg = Q + base + (size_t)qt * TQ_ * D_;
    const float* Kg = K + base;
    const float* Vg = V + base;
    const int*   Mg = M + (size_t)b * S_;
    float* Og = Out + base + (size_t)qt * TQ_ * D_;
    float* Ag = Out + (size_t)BH_ * S_ * D_ + (size_t)bh * S_ * S_ + (size_t)qt * TQ_ * S_;

    // ---- Load Q tile, scale by 1/temperature, bf16 hi/lo split into smem ----
#pragma unroll
    for (int i = 0; i < 8; i++) {
        int j = tid + THREADS_ * i;                 // float4 index, 2048 total
        float4 x = reinterpret_cast<const float4*>(Qg)[j];
        int row = j >> 4;
        int col = (j & 15) << 2;
        float vals[4] = {x.x, x.y, x.z, x.w};
#pragma unroll
        for (int c = 0; c < 4; c++) {
            float xv = vals[c] * 0.125f;
            __nv_bfloat16 h = __float2bfloat16(xv);
            sQh[row * ROWP_ + col + c] = h;
            sQl[row * ROWP_ + col + c] = __float2bfloat16(xv - __bfloat162float(h));
        }
    }
    __syncthreads();

    // ---- Persistent A fragments (this warp's 16 queries, full D=64) ----
    uint32_t aH[4][4], aL[4][4];
    {
        int r = wid * 16 + (lane & 15);
        int ch = (lane >> 4) * 8;
#pragma unroll
        for (int ds = 0; ds < 4; ds++) {
            ldsm_x4(aH[ds], smem_u32(&sQh[r * ROWP_ + ds * 16 + ch]));
            ldsm_x4(aL[ds], smem_u32(&sQl[r * ROWP_ + ds * 16 + ch]));
        }
    }

    const uint32_t bk_h = smem_u32(&sKh[(lane & 7) * ROWP_ + ((lane >> 3) & 1) * 8]);
    const uint32_t bk_l = smem_u32(&sKl[(lane & 7) * ROWP_ + ((lane >> 3) & 1) * 8]);
    const uint32_t bv_h = smem_u32(&sVh[(lane & 15) * ROWP_]);
    const uint32_t bv_l = smem_u32(&sVl[(lane & 15) * ROWP_]);
    const int row_stride_b = ROWP_ * 2;   // bytes per smem row

    // ======================= Phase 1: rowsums =======================
    float rs0 = 0.f, rs1 = 0.f;
    {
        float4 kr[4];
#pragma unroll
        for (int i = 0; i < 4; i++)
            kr[i] = reinterpret_cast<const float4*>(Kg)[tid + THREADS_ * i];
        int mreg = (tid < KT_) ? Mg[tid] : 0;

#pragma unroll 1
        for (int kt = 0; kt < NKT_; kt++) {
            // Store current K tile (bf16 hi/lo) + mask
#pragma unroll
            for (int i = 0; i < 4; i++) {
                int j = tid + THREADS_ * i;
                int row = j >> 4;
                int col = (j & 15) << 2;
                float vv[4] = {kr[i].x, kr[i].y, kr[i].z, kr[i].w};
#pragma unroll
                for (int c = 0; c < 4; c++) {
                    __nv_bfloat16 h = __float2bfloat16(vv[c]);
                    sKh[row * ROWP_ + col + c] = h;
                    sKl[row * ROWP_ + col + c] = __float2bfloat16(vv[c] - __bfloat162float(h));
                }
            }
            if (tid < KT_) smask[tid] = mreg;
            __syncthreads();

            // Prefetch next tile into registers (overlaps with compute)
            if (kt + 1 < NKT_) {
                const float4* nk = reinterpret_cast<const float4*>(Kg + (size_t)(kt + 1) * KT_ * D_);
#pragma unroll
                for (int i = 0; i < 4; i++) kr[i] = nk[tid + THREADS_ * i];
                if (tid < KT_) mreg = Mg[(kt + 1) * KT_ + tid];
            }

#pragma unroll
            for (int nt = 0; nt < 8; nt++) {
                float c[4] = {0.f, 0.f, 0.f, 0.f};
                qk_tile(c, aH, aL, bk_h + nt * 8 * row_stride_b, bk_l + nt * 8 * row_stride_b);
                int kc = nt * 8 + ((lane & 3) << 1);
                int m0 = smask[kc], m1 = smask[kc + 1];
                float p0 = m0 ? __expf(c[0]) : 0.f;
                float p1 = m1 ? __expf(c[1]) : 0.f;
                float p2 = m0 ? __expf(c[2]) : 0.f;
                float p3 = m1 ? __expf(c[3]) : 0.f;
                rs0 += p0 + p1;
                rs1 += p2 + p3;
            }
            __syncthreads();
        }
    }
    // Reduce rowsums across the 4 lanes sharing each row; store 1/rowsum.
    rs0 += __shfl_xor_sync(0xffffffffu, rs0, 1);
    rs0 += __shfl_xor_sync(0xffffffffu, rs0, 2);
    rs1 += __shfl_xor_sync(0xffffffffu, rs1, 1);
    rs1 += __shfl_xor_sync(0xffffffffu, rs1, 2);
    if ((lane & 3) == 0) {
        srs[wid * 16 + (lane >> 2)]     = 1.f / rs0;
        srs[wid * 16 + (lane >> 2) + 8] = 1.f / rs1;
    }
    __syncthreads();

    // ======================= Phase 2: attn + PV =======================
    const float inv0 = srs[wid * 16 + (lane >> 2)];
    const float inv1 = srs[wid * 16 + (lane >> 2) + 8];

    float o[8][4];
#pragma unroll
    for (int dn = 0; dn < 8; dn++)
#pragma unroll
        for (int c = 0; c < 4; c++) o[dn][c] = 0.f;

    {
        float4 kr[4], vr[4];
#pragma unroll
        for (int i = 0; i < 4; i++) {
            kr[i] = reinterpret_cast<const float4*>(Kg)[tid + THREADS_ * i];
            vr[i] = reinterpret_cast<const float4*>(Vg)[tid + THREADS_ * i];
        }
        int mreg = (tid < KT_) ? Mg[tid] : 0;

#pragma unroll 1
        for (int kt = 0; kt < NKT_; kt++) {
#pragma unroll
            for (int i = 0; i < 4; i++) {
                int j = tid + THREADS_ * i;
                int row = j >> 4;
                int col = (j & 15) << 2;
                float kk[4] = {kr[i].x, kr[i].y, kr[i].z, kr[i].w};
                float vvv[4] = {vr[i].x, vr[i].y, vr[i].z, vr[i].w};
#pragma unroll
                for (int c = 0; c < 4; c++) {
                    __nv_bfloat16 h = __float2bfloat16(kk[c]);
                    sKh[row * ROWP_ + col + c] = h;
                    sKl[row * ROWP_ + col + c] = __float2bfloat16(kk[c] - __bfloat162float(h));
                    __nv_bfloat16 hv = __float2bfloat16(vvv[c]);
                    sVh[row * ROWP_ + col + c] = hv;
                    sVl[row * ROWP_ + col + c] = __float2bfloat16(vvv[c] - __bfloat162float(hv));
                }
            }
            if (tid < KT_) smask[tid] = mreg;
            __syncthreads();

            if (kt + 1 < NKT_) {
                const float4* nk = reinterpret_cast<const float4*>(Kg + (size_t)(kt + 1) * KT_ * D_);
                const float4* nv = reinterpret_cast<const float4*>(Vg + (size_t)(kt + 1) * KT_ * D_);
#pragma unroll
                for (int i = 0; i < 4; i++) { kr[i] = nk[tid + THREADS_ * i]; vr[i] = nv[tid + THREADS_ * i]; }
                if (tid < KT_) mreg = Mg[(kt + 1) * KT_ + tid];
            }

            const int qr0 = wid * 16 + (lane >> 2);
#pragma unroll
            for (int nc = 0; nc < 4; nc++) {            // 16-key chunks
                const int n0 = nc * 16;
                float pn[2][4];
#pragma unroll
                for (int nt = 0; nt < 2; nt++) {
                    float c[4] = {0.f, 0.f, 0.f, 0.f};
                    qk_tile(c, aH, aL,
                            bk_h + (n0 + nt * 8) * row_stride_b,
                            bk_l + (n0 + nt * 8) * row_stride_b);
                    int kc = n0 + nt * 8 + ((lane & 3) << 1);
                    int m0 = smask[kc], m1 = smask[kc + 1];
                    pn[nt][0] = m0 ? __expf(c[0]) * inv0 : 0.f;
                    pn[nt][1] = m1 ? __expf(c[1]) * inv0 : 0.f;
                    pn[nt][2] = m0 ? __expf(c[2]) * inv1 : 0.f;
                    pn[nt][3] = m1 ? __expf(c[3]) * inv1 : 0.f;
                }

                // Write normalized attn (float2, full 32B sectors)
#pragma unroll
                for (int nt = 0; nt < 2; nt++) {
                    int col = kt * KT_ + n0 + nt * 8 + ((lane & 3) << 1);
                    *reinterpret_cast<float2*>(Ag + (size_t)qr0 * S_ + col) =
                        make_float2(pn[nt][0], pn[nt][1]);
                    *reinterpret_cast<float2*>(Ag + (size_t)(qr0 + 8) * S_ + col) =
                        make_float2(pn[nt][2], pn[nt][3]);
                }

                // Repack C-fragments directly as A-fragments for PV (layouts match)
                uint32_t ph[4], pl[4];
                split2(pn[0][0], pn[0][1], ph[0], pl[0]);
                split2(pn[0][2], pn[0][3], ph[1], pl[1]);
                split2(pn[1][0], pn[1][1], ph[2], pl[2]);
                split2(pn[1][2], pn[1][3], ph[3], pl[3]);

                const uint32_t vah = bv_h + n0 * row_stride_b;
                const uint32_t val_ = bv_l + n0 * row_stride_b;
#pragma unroll
                for (int dn = 0; dn < 8; dn++) {
                    uint32_t bvh2[2], bvl2[2];
                    ldsm_x2t(bvh2, vah + dn * 16);
                    ldsm_x2t(bvl2, val_ + dn * 16);
                    mma16816(o[dn], ph, bvh2);
                    mma16816(o[dn], ph, bvl2);
                    mma16816(o[dn], pl, bvh2);
                }
            }
            __syncthreads();
        }
    }

    // ---- Write output (already normalized: P was normalized before PV) ----
    {
        const int qr0 = wid * 16 + (lane >> 2);
#pragma unroll
        for (int dn = 0; dn < 8; dn++) {
            int col = dn * 8 + ((lane & 3) << 1);
            *reinterpret_cast<float2*>(Og + (size_t)qr0 * D_ + col) =
                make_float2(o[dn][0], o[dn][1]);
            *reinterpret_cast<float2*>(Og + (size_t)(qr0 + 8) * D_ + col) =
                make_float2(o[dn][2], o[dn][3]);
        }
    }
}

} // namespace

extern "C" void kernel_launch(void* const* d_in, const int* in_sizes, int n_in,
                              void* d_out, int out_size) {
    (void)in_sizes; (void)n_in; (void)out_size;
    const float* q = (const float*)d_in[0];
    const float* k = (const float*)d_in[1];
    const float* v = (const float*)d_in[2];
    const int*   m = (const int*)d_in[3];
    float* out = (float*)d_out;

    cudaFuncSetAttribute(attn_kernel, cudaFuncAttributeMaxDynamicSharedMemorySize, SMEM_BYTES);
    dim3 grid(S_ / TQ_, BH_);   // x = q-tile (fast-varying -> same bh adjacent for L2 K/V reuse)
    attn_kernel<<<grid, THREADS_, SMEM_BYTES>>>(q, k, v, m, out);
}

// round 2
// speedup vs baseline: 1.0119x; 1.0119x over previous
#include <cuda_runtime.h>
#include <cuda_bf16.h>
#include <cstdint>

// ============================================================================
// Fused SDPA with attn-matrix output (recompute two-phase, 3-split bf16 mma).
// R2: 2 CTAs/SM (launch_bounds 256,2), double-buffered K/V tiles (1 sync/tile),
//     split accumulator chains, float mask multiplier, streaming attn stores.
// ============================================================================

namespace {

constexpr int S_  = 2048;
constexpr int D_  = 64;
constexpr int BH_ = 32;          // B*H
constexpr int TQ_ = 128;         // queries per CTA
constexpr int KT_ = 64;          // keys per smem tile
constexpr int NKT_ = S_ / KT_;   // 32 key tiles
constexpr int THREADS_ = 256;    // 8 warps, warp w owns queries [16w,16w+16)
constexpr int ROWP_ = 72;        // padded bf16 row (144B): conflict-free LDSM

// smem layout (bytes)
constexpr int SQH_OFF = 0;
constexpr int SQL_OFF = SQH_OFF + TQ_ * ROWP_ * 2;        // 18432
constexpr int BUF_OFF = SQL_OFF + TQ_ * ROWP_ * 2;        // 36864
// per-buffer block: Kh, Kl, Vh, Vl (9216 each) + mask floats (256)
constexpr int KH_  = 0;
constexpr int KL_  = KH_ + KT_ * ROWP_ * 2;
constexpr int VH_  = KL_ + KT_ * ROWP_ * 2;
constexpr int VL_  = VH_ + KT_ * ROWP_ * 2;
constexpr int MSK_ = VL_ + KT_ * ROWP_ * 2;               // 36864 within block
constexpr int BLK_SZ = MSK_ + KT_ * 4;                    // 37120
constexpr int SRS_OFF = BUF_OFF + 2 * BLK_SZ;             // 111104
constexpr int SMEM_BYTES = SRS_OFF + TQ_ * 4;             // 111616

__device__ __forceinline__ uint32_t smem_u32(const void* p) {
    return (uint32_t)__cvta_generic_to_shared(p);
}
__device__ __forceinline__ void ldsm_x4(uint32_t a[4], uint32_t addr) {
    asm volatile("ldmatrix.sync.aligned.m8n8.x4.shared.b16 {%0,%1,%2,%3}, [%4];"
                 : "=r"(a[0]), "=r"(a[1]), "=r"(a[2]), "=r"(a[3]) : "r"(addr));
}
__device__ __forceinline__ void ldsm_x2(uint32_t b[2], uint32_t addr) {
    asm volatile("ldmatrix.sync.aligned.m8n8.x2.shared.b16 {%0,%1}, [%2];"
                 : "=r"(b[0]), "=r"(b[1]) : "r"(addr));
}
__device__ __forceinline__ void ldsm_x2t(uint32_t b[2], uint32_t addr) {
    asm volatile("ldmatrix.sync.aligned.m8n8.x2.trans.shared.b16 {%0,%1}, [%2];"
                 : "=r"(b[0]), "=r"(b[1]) : "r"(addr));
}
__device__ __forceinline__ void mma16816(float c[4], const uint32_t a[4], const uint32_t b[2]) {
    asm volatile(
        "mma.sync.aligned.m16n8k16.row.col.f32.bf16.bf16.f32 "
        "{%0,%1,%2,%3}, {%4,%5,%6,%7}, {%8,%9}, {%0,%1,%2,%3};"
        : "+f"(c[0]), "+f"(c[1]), "+f"(c[2]), "+f"(c[3])
        : "r"(a[0]), "r"(a[1]), "r"(a[2]), "r"(a[3]), "r"(b[0]), "r"(b[1]));
}
__device__ __forceinline__ void split2(float x, float y, uint32_t& hi, uint32_t& lo) {
    __nv_bfloat16 hx = __float2bfloat16(x);
    __nv_bfloat16 hy = __float2bfloat16(y);
    hi = ((uint32_t)__bfloat16_as_ushort(hy) << 16) | (uint32_t)__bfloat16_as_ushort(hx);
    __nv_bfloat16 lx = __float2bfloat16(x - __bfloat162float(hx));
    __nv_bfloat16 ly = __float2bfloat16(y - __bfloat162float(hy));
    lo = ((uint32_t)__bfloat16_as_ushort(ly) << 16) | (uint32_t)__bfloat16_as_ushort(lx);
}

// One 16x8 QK score tile: hi*hi into c (4-chain), cross terms into cE (8-chain).
__device__ __forceinline__ void qk_tile(float c[4],
                                        const uint32_t aH[4][4], const uint32_t aL[4][4],
                                        uint32_t bah, uint32_t bal) {
    float cE[4] = {0.f, 0.f, 0.f, 0.f};
#pragma unroll
    for (int ds = 0; ds < 4; ds++) {
        uint32_t bh2[2], bl2[2];
        ldsm_x2(bh2, bah + ds * 32);
        ldsm_x2(bl2, bal + ds * 32);
        mma16816(c, aH[ds], bh2);
        mma16816(cE, aH[ds], bl2);
        mma16816(cE, aL[ds], bh2);
    }
#pragma unroll
    for (int i = 0; i < 4; i++) c[i] += cE[i];
}

__global__ void __launch_bounds__(THREADS_, 2)
attn_kernel(const float* __restrict__ Q, const float* __restrict__ K,
            const float* __restrict__ V, const int* __restrict__ M,
            float* __restrict__ Out) {
    extern __shared__ char smem[];
    __nv_bfloat16* sQh = (__nv_bfloat16*)(smem + SQH_OFF);
    __nv_bfloat16* sQl = (__nv_bfloat16*)(smem + SQL_OFF);
    float* srs = (float*)(smem + SRS_OFF);

    char* blk[2] = {smem + BUF_OFF, smem + BUF_OFF + BLK_SZ};

    const int qt = blockIdx.x;
    const int bh = blockIdx.y;
    const int tid = threadIdx.x;
    const int wid = tid >> 5;
    const int lane = tid & 31;
    const int b = bh >> 4;  // H = 16

    const size_t base = (size_t)bh * S_ * D_;
    const float* Qg = Q + base + (size_t)qt * TQ_ * D_;
    const float* Kg = K + base;
    const float* Vg = V + base;
    const int*   Mg = M + (size_t)b * S_;
    float* Og = Out + base + (size_t)qt * TQ_ * D_;
    float* Ag = Out + (size_t)BH_ * S_ * D_ + (size_t)bh * S_ * S_ + (size_t)qt * TQ_ * S_;

    // ---- Load Q tile, scale by 1/temperature, bf16 hi/lo split into smem ----
#pragma unroll
    for (int i = 0; i < 8; i++) {
        int j = tid + THREADS_ * i;                 // float4 index, 2048 total
        float4 x = reinterpret_cast<const float4*>(Qg)[j];
        int row = j >> 4;
        int col = (j & 15) << 2;
        float vals[4] = {x.x, x.y, x.z, x.w};
#pragma unroll
        for (int c = 0; c < 4; c++) {
            float xv = vals[c] * 0.125f;
            __nv_bfloat16 h = __float2bfloat16(xv);
            sQh[row * ROWP_ + col + c] = h;
            sQl[row * ROWP_ + col + c] = __float2bfloat16(xv - __bfloat162float(h));
        }
    }
    __syncthreads();

    // ---- Persistent A fragments (this warp's 16 queries, full D=64) ----
    uint32_t aH[4][4], aL[4][4];
    {
        int r = wid * 16 + (lane & 15);
        int ch = (lane >> 4) * 8;
#pragma unroll
        for (int ds = 0; ds < 4; ds++) {
            ldsm_x4(aH[ds], smem_u32(&sQh[r * ROWP_ + ds * 16 + ch]));
            ldsm_x4(aL[ds], smem_u32(&sQl[r * ROWP_ + ds * 16 + ch]));
        }
    }

    // Per-buffer ldmatrix base addresses
    uint32_t bkh[2], bkl[2], bvh[2], bvl[2];
#pragma unroll
    for (int u = 0; u < 2; u++) {
        uint32_t koff = ((lane & 7) * ROWP_ + ((lane >> 3) & 1) * 8) * 2;
        uint32_t voff = (lane & 15) * ROWP_ * 2;
        bkh[u] = smem_u32(blk[u] + KH_) + koff;
        bkl[u] = smem_u32(blk[u] + KL_) + koff;
        bvh[u] = smem_u32(blk[u] + VH_) + voff;
        bvl[u] = smem_u32(blk[u] + VL_) + voff;
    }
    const int rsb = ROWP_ * 2;   // bytes per smem row

    // ======================= Phase 1: rowsums =======================
    float rs0 = 0.f, rs1 = 0.f;
    {
        // preload tile 0 into buf 0
        {
            float4 kr[4];
#pragma unroll
            for (int i = 0; i < 4; i++)
                kr[i] = reinterpret_cast<const float4*>(Kg)[tid + THREADS_ * i];
            __nv_bfloat16* kh = (__nv_bfloat16*)(blk[0] + KH_);
            __nv_bfloat16* kl = (__nv_bfloat16*)(blk[0] + KL_);
#pragma unroll
            for (int i = 0; i < 4; i++) {
                int j = tid + THREADS_ * i;
                int row = j >> 4, col = (j & 15) << 2;
                float vv[4] = {kr[i].x, kr[i].y, kr[i].z, kr[i].w};
#pragma unroll
                for (int c = 0; c < 4; c++) {
                    __nv_bfloat16 h = __float2bfloat16(vv[c]);
                    kh[row * ROWP_ + col + c] = h;
                    kl[row * ROWP_ + col + c] = __float2bfloat16(vv[c] - __bfloat162float(h));
                }
            }
            if (tid < KT_) ((float*)(blk[0] + MSK_))[tid] = Mg[tid] ? 1.f : 0.f;
        }
        __syncthreads();

#pragma unroll 1
        for (int kt = 0; kt < NKT_; kt++) {
            const int buf = kt & 1;
            const float* msk = (const float*)(blk[buf] + MSK_);
            const bool pre = (kt + 1 < NKT_);

            float4 kr[4];
            int mreg = 0;
            if (pre) {
                const float4* nk = reinterpret_cast<const float4*>(Kg + (size_t)(kt + 1) * KT_ * D_);
#pragma unroll
                for (int i = 0; i < 4; i++) kr[i] = nk[tid + THREADS_ * i];
                if (tid < KT_) mreg = Mg[(kt + 1) * KT_ + tid];
            }

#pragma unroll
            for (int nt = 0; nt < 4; nt++) {
                float c[4] = {0.f, 0.f, 0.f, 0.f};
                qk_tile(c, aH, aL, bkh[buf] + nt * 8 * rsb, bkl[buf] + nt * 8 * rsb);
                int kc = nt * 8 + ((lane & 3) << 1);
                float m0 = msk[kc], m1 = msk[kc + 1];
                rs0 += m0 * __expf(c[0]) + m1 * __expf(c[1]);
                rs1 += m0 * __expf(c[2]) + m1 * __expf(c[3]);
            }

            if (pre) {
                __nv_bfloat16* kh = (__nv_bfloat16*)(blk[buf ^ 1] + KH_);
                __nv_bfloat16* kl = (__nv_bfloat16*)(blk[buf ^ 1] + KL_);
#pragma unroll
                for (int i = 0; i < 4; i++) {
                    int j = tid + THREADS_ * i;
                    int row = j >> 4, col = (j & 15) << 2;
                    float vv[4] = {kr[i].x, kr[i].y, kr[i].z, kr[i].w};
#pragma unroll
                    for (int c = 0; c < 4; c++) {
                        __nv_bfloat16 h = __float2bfloat16(vv[c]);
                        kh[row * ROWP_ + col + c] = h;
                        kl[row * ROWP_ + col + c] = __float2bfloat16(vv[c] - __bfloat162float(h));
                    }
                }
                if (tid < KT_) ((float*)(blk[buf ^ 1] + MSK_))[tid] = mreg ? 1.f : 0.f;
            }

#pragma unroll
            for (int nt = 4; nt < 8; nt++) {
                float c[4] = {0.f, 0.f, 0.f, 0.f};
                qk_tile(c, aH, aL, bkh[buf] + nt * 8 * rsb, bkl[buf] + nt * 8 * rsb);
                int kc = nt * 8 + ((lane & 3) << 1);
                float m0 = msk[kc], m1 = msk[kc + 1];
                rs0 += m0 * __expf(c[0]) + m1 * __expf(c[1]);
                rs1 += m0 * __expf(c[2]) + m1 * __expf(c[3]);
            }
            __syncthreads();
        }
    }
    // Reduce rowsums across the 4 lanes sharing each row; store 1/rowsum.
    rs0 += __shfl_xor_sync(0xffffffffu, rs0, 1);
    rs0 += __shfl_xor_sync(0xffffffffu, rs0, 2);
    rs1 += __shfl_xor_sync(0xffffffffu, rs1, 1);
    rs1 += __shfl_xor_sync(0xffffffffu, rs1, 2);
    if ((lane & 3) == 0) {
        srs[wid * 16 + (lane >> 2)]     = 1.f / rs0;
        srs[wid * 16 + (lane >> 2) + 8] = 1.f / rs1;
    }
    __syncthreads();

    // ======================= Phase 2: attn + PV =======================
    const float inv0 = srs[wid * 16 + (lane >> 2)];
    const float inv1 = srs[wid * 16 + (lane >> 2) + 8];
    const int qr0 = wid * 16 + (lane >> 2);

    float o[8][4];
#pragma unroll
    for (int dn = 0; dn < 8; dn++)
#pragma unroll
        for (int c = 0; c < 4; c++) o[dn][c] = 0.f;

    {
        // preload tile 0 (K + V) into buf 0
        {
            float4 kr[4], vr[4];
#pragma unroll
            for (int i = 0; i < 4; i++) {
                kr[i] = reinterpret_cast<const float4*>(Kg)[tid + THREADS_ * i];
                vr[i] = reinterpret_cast<const float4*>(Vg)[tid + THREADS_ * i];
            }
            __nv_bfloat16* kh = (__nv_bfloat16*)(blk[0] + KH_);
            __nv_bfloat16* kl = (__nv_bfloat16*)(blk[0] + KL_);
            __nv_bfloat16* vh = (__nv_bfloat16*)(blk[0] + VH_);
            __nv_bfloat16* vl = (__nv_bfloat16*)(blk[0] + VL_);
#pragma unroll
            for (int i = 0; i < 4; i++) {
                int j = tid + THREADS_ * i;
                int row = j >> 4, col = (j & 15) << 2;
                float kk[4] = {kr[i].x, kr[i].y, kr[i].z, kr[i].w};
                float vv[4] = {vr[i].x, vr[i].y, vr[i].z, vr[i].w};
#pragma unroll
                for (int c = 0; c < 4; c++) {
                    __nv_bfloat16 h = __float2bfloat16(kk[c]);
                    kh[row * ROWP_ + col + c] = h;
                    kl[row * ROWP_ + col + c] = __float2bfloat16(kk[c] - __bfloat162float(h));
                    __nv_bfloat16 hv = __float2bfloat16(vv[c]);
                    vh[row * ROWP_ + col + c] = hv;
                    vl[row * ROWP_ + col + c] = __float2bfloat16(vv[c] - __bfloat162float(hv));
                }
            }
            if (tid < KT_) ((float*)(blk[0] + MSK_))[tid] = Mg[tid] ? 1.f : 0.f;
        }
        __syncthreads();

#pragma unroll 1
        for (int kt = 0; kt < NKT_; kt++) {
            const int buf = kt & 1;
            const float* msk = (const float*)(blk[buf] + MSK_);
            const bool pre = (kt + 1 < NKT_);

            float4 kr[4], vr[4];
            int mreg = 0;
            if (pre) {
                const float4* nk = reinterpret_cast<const float4*>(Kg + (size_t)(kt + 1) * KT_ * D_);
                const float4* nv = reinterpret_cast<const float4*>(Vg + (size_t)(kt + 1) * KT_ * D_);
#pragma unroll
                for (int i = 0; i < 4; i++) { kr[i] = nk[tid + THREADS_ * i]; vr[i] = nv[tid + THREADS_ * i]; }
                if (tid < KT_) mreg = Mg[(kt + 1) * KT_ + tid];
            }

#pragma unroll
            for (int nc = 0; nc < 4; nc++) {            // 16-key chunks
                const int n0 = nc * 16;
                float pn[2][4];
#pragma unroll
                for (int nt = 0; nt < 2; nt++) {
                    float c[4] = {0.f, 0.f, 0.f, 0.f};
                    qk_tile(c, aH, aL,
                            bkh[buf] + (n0 + nt * 8) * rsb,
                            bkl[buf] + (n0 + nt * 8) * rsb);
                    int kc = n0 + nt * 8 + ((lane & 3) << 1);
                    float m0 = msk[kc], m1 = msk[kc + 1];
                    pn[nt][0] = m0 * __expf(c[0]) * inv0;
                    pn[nt][1] = m1 * __expf(c[1]) * inv0;
                    pn[nt][2] = m0 * __expf(c[2]) * inv1;
                    pn[nt][3] = m1 * __expf(c[3]) * inv1;
                }

                // Streaming write of normalized attn
#pragma unroll
                for (int nt = 0; nt < 2; nt++) {
                    int col = kt * KT_ + n0 + nt * 8 + ((lane & 3) << 1);
                    __stwt(reinterpret_cast<float2*>(Ag + (size_t)qr0 * S_ + col),
                           make_float2(pn[nt][0], pn[nt][1]));
                    __stwt(reinterpret_cast<float2*>(Ag + (size_t)(qr0 + 8) * S_ + col),
                           make_float2(pn[nt][2], pn[nt][3]));
                }

                // Repack C-fragments directly as A-fragments for PV
                uint32_t ph[4], pl[4];
                split2(pn[0][0], pn[0][1], ph[0], pl[0]);
                split2(pn[0][2], pn[0][3], ph[1], pl[1]);
                split2(pn[1][0], pn[1][1], ph[2], pl[2]);
                split2(pn[1][2], pn[1][3], ph[3], pl[3]);

                const uint32_t vah = bvh[buf] + n0 * rsb;
                const uint32_t val_ = bvl[buf] + n0 * rsb;
#pragma unroll
                for (int dn = 0; dn < 8; dn++) {
                    uint32_t bvh2[2], bvl2[2];
                    ldsm_x2t(bvh2, vah + dn * 16);
                    ldsm_x2t(bvl2, val_ + dn * 16);
                    mma16816(o[dn], ph, bvh2);
                    mma16816(o[dn], ph, bvl2);
                    mma16816(o[dn], pl, bvh2);
                }

                // After first half of the tile's compute, commit the prefetch
                if (nc == 1 && pre) {
                    __nv_bfloat16* kh = (__nv_bfloat16*)(blk[buf ^ 1] + KH_);
                    __nv_bfloat16* kl = (__nv_bfloat16*)(blk[buf ^ 1] + KL_);
                    __nv_bfloat16* vh = (__nv_bfloat16*)(blk[buf ^ 1] + VH_);
                    __nv_bfloat16* vl = (__nv_bfloat16*)(blk[buf ^ 1] + VL_);
#pragma unroll
                    for (int i = 0; i < 4; i++) {
                        int j = tid + THREADS_ * i;
                        int row = j >> 4, col = (j & 15) << 2;
                        float kk[4] = {kr[i].x, kr[i].y, kr[i].z, kr[i].w};
                        float vv[4] = {vr[i].x, vr[i].y, vr[i].z, vr[i].w};
#pragma unroll
                        for (int c = 0; c < 4; c++) {
                            __nv_bfloat16 h = __float2bfloat16(kk[c]);
                            kh[row * ROWP_ + col + c] = h;
                            kl[row * ROWP_ + col + c] = __float2bfloat16(kk[c] - __bfloat162float(h));
                            __nv_bfloat16 hv = __float2bfloat16(vv[c]);
                            vh[row * ROWP_ + col + c] = hv;
                            vl[row * ROWP_ + col + c] = __float2bfloat16(vv[c] - __bfloat162float(hv));
                        }
                    }
                    if (tid < KT_) ((float*)(blk[buf ^ 1] + MSK_))[tid] = mreg ? 1.f : 0.f;
                }
            }
            __syncthreads();
        }
    }

    // ---- Write output (P was normalized before PV) ----
#pragma unroll
    for (int dn = 0; dn < 8; dn++) {
        int col = dn * 8 + ((lane & 3) << 1);
        *reinterpret_cast<float2*>(Og + (size_t)qr0 * D_ + col) =
            make_float2(o[dn][0], o[dn][1]);
        *reinterpret_cast<float2*>(Og + (size_t)(qr0 + 8) * D_ + col) =
            make_float2(o[dn][2], o[dn][3]);
    }
}

} // namespace

extern "C" void kernel_launch(void* const* d_in, const int* in_sizes, int n_in,
                              void* d_out, int out_size) {
    (void)in_sizes; (void)n_in; (void)out_size;
    const float* q = (const float*)d_in[0];
    const float* k = (const float*)d_in[1];
    const float* v = (const float*)d_in[2];
    const int*   m = (const int*)d_in[3];
    float* out = (float*)d_out;

    cudaFuncSetAttribute(attn_kernel, cudaFuncAttributeMaxDynamicSharedMemorySize, SMEM_BYTES);
    dim3 grid(S_ / TQ_, BH_);   // x = q-tile fast-varying -> L2 K/V reuse within bh
    attn_kernel<<<grid, THREADS_, SMEM_BYTES>>>(q, k, v, m, out);
}

// round 3
// speedup vs baseline: 1.0491x; 1.0367x over previous
#include <cuda_runtime.h>
#include <cuda_bf16.h>
#include <cstdint>

// ============================================================================
// Fused SDPA with attn-matrix output — single compute pass + normalize sweep.
//   Pass 1: QK (3-split bf16 mma) -> p = mask*exp(score) (UNNORMALIZED)
//           -> write p to attn buffer, accumulate rowsums, PV mma with p.
//   Pass 2: out = acc / rowsum;  attn tile re-read, scaled by 1/rowsum,
//           streamed back (__stwt). No QK recompute anywhere.
// ============================================================================

namespace {

constexpr int S_  = 2048;
constexpr int D_  = 64;
constexpr int BH_ = 32;          // B*H
constexpr int TQ_ = 128;         // queries per CTA
constexpr int KT_ = 64;          // keys per smem tile
constexpr int NKT_ = S_ / KT_;   // 32 key tiles
constexpr int THREADS_ = 256;    // 8 warps, warp w owns queries [16w,16w+16)
constexpr int ROWP_ = 72;        // padded bf16 row (144B): conflict-free LDSM

// smem layout (bytes)
constexpr int SQH_OFF = 0;
constexpr int SQL_OFF = SQH_OFF + TQ_ * ROWP_ * 2;        // 18432
constexpr int BUF_OFF = SQL_OFF + TQ_ * ROWP_ * 2;        // 36864
constexpr int KH_  = 0;
constexpr int KL_  = KH_ + KT_ * ROWP_ * 2;
constexpr int VH_  = KL_ + KT_ * ROWP_ * 2;
constexpr int VL_  = VH_ + KT_ * ROWP_ * 2;
constexpr int MSK_ = VL_ + KT_ * ROWP_ * 2;
constexpr int BLK_SZ = MSK_ + KT_ * 4;                    // 37120
constexpr int SRS_OFF = BUF_OFF + 2 * BLK_SZ;             // 111104
constexpr int SMEM_BYTES = SRS_OFF + TQ_ * 4;             // 111616

__device__ __forceinline__ uint32_t smem_u32(const void* p) {
    return (uint32_t)__cvta_generic_to_shared(p);
}
__device__ __forceinline__ void ldsm_x4(uint32_t a[4], uint32_t addr) {
    asm volatile("ldmatrix.sync.aligned.m8n8.x4.shared.b16 {%0,%1,%2,%3}, [%4];"
                 : "=r"(a[0]), "=r"(a[1]), "=r"(a[2]), "=r"(a[3]) : "r"(addr));
}
__device__ __forceinline__ void ldsm_x2(uint32_t b[2], uint32_t addr) {
    asm volatile("ldmatrix.sync.aligned.m8n8.x2.shared.b16 {%0,%1}, [%2];"
                 : "=r"(b[0]), "=r"(b[1]) : "r"(addr));
}
__device__ __forceinline__ void ldsm_x2t(uint32_t b[2], uint32_t addr) {
    asm volatile("ldmatrix.sync.aligned.m8n8.x2.trans.shared.b16 {%0,%1}, [%2];"
                 : "=r"(b[0]), "=r"(b[1]) : "r"(addr));
}
__device__ __forceinline__ void mma16816(float c[4], const uint32_t a[4], const uint32_t b[2]) {
    asm volatile(
        "mma.sync.aligned.m16n8k16.row.col.f32.bf16.bf16.f32 "
        "{%0,%1,%2,%3}, {%4,%5,%6,%7}, {%8,%9}, {%0,%1,%2,%3};"
        : "+f"(c[0]), "+f"(c[1]), "+f"(c[2]), "+f"(c[3])
        : "r"(a[0]), "r"(a[1]), "r"(a[2]), "r"(a[3]), "r"(b[0]), "r"(b[1]));
}
__device__ __forceinline__ uint32_t pack_bf16(__nv_bfloat16 lo, __nv_bfloat16 hi) {
    return ((uint32_t)__bfloat16_as_ushort(hi) << 16) | (uint32_t)__bfloat16_as_ushort(lo);
}
__device__ __forceinline__ void split2(float x, float y, uint32_t& hi, uint32_t& lo) {
    __nv_bfloat16 hx = __float2bfloat16(x);
    __nv_bfloat16 hy = __float2bfloat16(y);
    hi = pack_bf16(hx, hy);
    lo = pack_bf16(__float2bfloat16(x - __bfloat162float(hx)),
                   __float2bfloat16(y - __bfloat162float(hy)));
}
// Split 4 consecutive floats into hi/lo bf16 and store as one uint2 each.
__device__ __forceinline__ void split_store4(__nv_bfloat16* hb, __nv_bfloat16* lb,
                                             int idx, float v0, float v1, float v2, float v3) {
    __nv_bfloat16 h0 = __float2bfloat16(v0), h1 = __float2bfloat16(v1);
    __nv_bfloat16 h2 = __float2bfloat16(v2), h3 = __float2bfloat16(v3);
    *reinterpret_cast<uint2*>(hb + idx) =
        make_uint2(pack_bf16(h0, h1), pack_bf16(h2, h3));
    __nv_bfloat16 l0 = __float2bfloat16(v0 - __bfloat162float(h0));
    __nv_bfloat16 l1 = __float2bfloat16(v1 - __bfloat162float(h1));
    __nv_bfloat16 l2 = __float2bfloat16(v2 - __bfloat162float(h2));
    __nv_bfloat16 l3 = __float2bfloat16(v3 - __bfloat162float(h3));
    *reinterpret_cast<uint2*>(lb + idx) =
        make_uint2(pack_bf16(l0, l1), pack_bf16(l2, l3));
}

// One 16x8 QK score tile: hi*hi into c (4-chain), cross terms into cE (8-chain).
__device__ __forceinline__ void qk_tile(float c[4],
                                        const uint32_t aH[4][4], const uint32_t aL[4][4],
                                        uint32_t bah, uint32_t bal) {
    float cE[4] = {0.f, 0.f, 0.f, 0.f};
#pragma unroll
    for (int ds = 0; ds < 4; ds++) {
        uint32_t bh2[2], bl2[2];
        ldsm_x2(bh2, bah + ds * 32);
        ldsm_x2(bl2, bal + ds * 32);
        mma16816(c, aH[ds], bh2);
        mma16816(cE, aH[ds], bl2);
        mma16816(cE, aL[ds], bh2);
    }
#pragma unroll
    for (int i = 0; i < 4; i++) c[i] += cE[i];
}

__global__ void __launch_bounds__(THREADS_, 2)
attn_kernel(const float* __restrict__ Q, const float* __restrict__ K,
            const float* __restrict__ V, const int* __restrict__ M,
            float* __restrict__ Out) {
    extern __shared__ char smem[];
    __nv_bfloat16* sQh = (__nv_bfloat16*)(smem + SQH_OFF);
    __nv_bfloat16* sQl = (__nv_bfloat16*)(smem + SQL_OFF);
    float* srs = (float*)(smem + SRS_OFF);
    char* blk[2] = {smem + BUF_OFF, smem + BUF_OFF + BLK_SZ};

    const int qt = blockIdx.x;
    const int bh = blockIdx.y;
    const int tid = threadIdx.x;
    const int wid = tid >> 5;
    const int lane = tid & 31;
    const int b = bh >> 4;  // H = 16

    const size_t base = (size_t)bh * S_ * D_;
    const float* Qg = Q + base + (size_t)qt * TQ_ * D_;
    const float* Kg = K + base;
    const float* Vg = V + base;
    const int*   Mg = M + (size_t)b * S_;
    float* Og = Out + base + (size_t)qt * TQ_ * D_;
    float* Ag = Out + (size_t)BH_ * S_ * D_ + (size_t)bh * S_ * S_ + (size_t)qt * TQ_ * S_;

    // ---- Load Q tile, scale by 1/temperature, bf16 hi/lo split into smem ----
#pragma unroll
    for (int i = 0; i < 8; i++) {
        int j = tid + THREADS_ * i;                 // float4 index, 2048 total
        float4 x = reinterpret_cast<const float4*>(Qg)[j];
        int idx = (j >> 4) * ROWP_ + ((j & 15) << 2);
        split_store4(sQh, sQl, idx, x.x * 0.125f, x.y * 0.125f, x.z * 0.125f, x.w * 0.125f);
    }
    __syncthreads();

    // ---- Persistent A fragments (this warp's 16 queries, full D=64) ----
    uint32_t aH[4][4], aL[4][4];
    {
        int r = wid * 16 + (lane & 15);
        int ch = (lane >> 4) * 8;
#pragma unroll
        for (int ds = 0; ds < 4; ds++) {
            ldsm_x4(aH[ds], smem_u32(&sQh[r * ROWP_ + ds * 16 + ch]));
            ldsm_x4(aL[ds], smem_u32(&sQl[r * ROWP_ + ds * 16 + ch]));
        }
    }

    uint32_t bkh[2], bkl[2], bvh[2], bvl[2];
#pragma unroll
    for (int u = 0; u < 2; u++) {
        uint32_t koff = ((lane & 7) * ROWP_ + ((lane >> 3) & 1) * 8) * 2;
        uint32_t voff = (lane & 15) * ROWP_ * 2;
        bkh[u] = smem_u32(blk[u] + KH_) + koff;
        bkl[u] = smem_u32(blk[u] + KL_) + koff;
        bvh[u] = smem_u32(blk[u] + VH_) + voff;
        bvl[u] = smem_u32(blk[u] + VL_) + voff;
    }
    const int rsb = ROWP_ * 2;   // bytes per smem row
    const int qr0 = wid * 16 + (lane >> 2);

    float rs0 = 0.f, rs1 = 0.f;
    float o[8][4];
#pragma unroll
    for (int dn = 0; dn < 8; dn++)
#pragma unroll
        for (int c = 0; c < 4; c++) o[dn][c] = 0.f;

    // ---- Preload tile 0 (K + V + mask) into buf 0 ----
    {
        float4 kr[4], vr[4];
#pragma unroll
        for (int i = 0; i < 4; i++) {
            kr[i] = reinterpret_cast<const float4*>(Kg)[tid + THREADS_ * i];
            vr[i] = reinterpret_cast<const float4*>(Vg)[tid + THREADS_ * i];
        }
        __nv_bfloat16* kh = (__nv_bfloat16*)(blk[0] + KH_);
        __nv_bfloat16* kl = (__nv_bfloat16*)(blk[0] + KL_);
        __nv_bfloat16* vh = (__nv_bfloat16*)(blk[0] + VH_);
        __nv_bfloat16* vl = (__nv_bfloat16*)(blk[0] + VL_);
#pragma unroll
        for (int i = 0; i < 4; i++) {
            int j = tid + THREADS_ * i;
            int idx = (j >> 4) * ROWP_ + ((j & 15) << 2);
            split_store4(kh, kl, idx, kr[i].x, kr[i].y, kr[i].z, kr[i].w);
            split_store4(vh, vl, idx, vr[i].x, vr[i].y, vr[i].z, vr[i].w);
        }
        if (tid < KT_) ((float*)(blk[0] + MSK_))[tid] = Mg[tid] ? 1.f : 0.f;
    }
    __syncthreads();

    // ======================= Single compute pass =======================
#pragma unroll 1
    for (int kt = 0; kt < NKT_; kt++) {
        const int buf = kt & 1;
        const float* msk = (const float*)(blk[buf] + MSK_);
        const bool pre = (kt + 1 < NKT_);

        float4 kr[4], vr[4];
        int mreg = 0;
        if (pre) {
            const float4* nk = reinterpret_cast<const float4*>(Kg + (size_t)(kt + 1) * KT_ * D_);
            const float4* nv = reinterpret_cast<const float4*>(Vg + (size_t)(kt + 1) * KT_ * D_);
#pragma unroll
            for (int i = 0; i < 4; i++) { kr[i] = nk[tid + THREADS_ * i]; vr[i] = nv[tid + THREADS_ * i]; }
            if (tid < KT_) mreg = Mg[(kt + 1) * KT_ + tid];
        }

#pragma unroll
        for (int nc = 0; nc < 4; nc++) {            // 16-key chunks
            const int n0 = nc * 16;
            float pn[2][4];
#pragma unroll
            for (int nt = 0; nt < 2; nt++) {
                float c[4] = {0.f, 0.f, 0.f, 0.f};
                qk_tile(c, aH, aL,
                        bkh[buf] + (n0 + nt * 8) * rsb,
                        bkl[buf] + (n0 + nt * 8) * rsb);
                int kc = n0 + nt * 8 + ((lane & 3) << 1);
                float m0 = msk[kc], m1 = msk[kc + 1];
                pn[nt][0] = m0 * __expf(c[0]);
                pn[nt][1] = m1 * __expf(c[1]);
                pn[nt][2] = m0 * __expf(c[2]);
                pn[nt][3] = m1 * __expf(c[3]);
                rs0 += pn[nt][0] + pn[nt][1];
                rs1 += pn[nt][2] + pn[nt][3];
            }

            // Write UNNORMALIZED p (regular stores -> L2-resident for readback)
#pragma unroll
            for (int nt = 0; nt < 2; nt++) {
                int col = kt * KT_ + n0 + nt * 8 + ((lane & 3) << 1);
                *reinterpret_cast<float2*>(Ag + (size_t)qr0 * S_ + col) =
                    make_float2(pn[nt][0], pn[nt][1]);
                *reinterpret_cast<float2*>(Ag + (size_t)(qr0 + 8) * S_ + col) =
                    make_float2(pn[nt][2], pn[nt][3]);
            }

            // Repack C-fragments directly as A-fragments for PV
            uint32_t ph[4], pl[4];
            split2(pn[0][0], pn[0][1], ph[0], pl[0]);
            split2(pn[0][2], pn[0][3], ph[1], pl[1]);
            split2(pn[1][0], pn[1][1], ph[2], pl[2]);
            split2(pn[1][2], pn[1][3], ph[3], pl[3]);

            const uint32_t vah = bvh[buf] + n0 * rsb;
            const uint32_t val_ = bvl[buf] + n0 * rsb;
#pragma unroll
            for (int dn = 0; dn < 8; dn++) {
                uint32_t bvh2[2], bvl2[2];
                ldsm_x2t(bvh2, vah + dn * 16);
                ldsm_x2t(bvl2, val_ + dn * 16);
                mma16816(o[dn], ph, bvh2);
                mma16816(o[dn], ph, bvl2);
                mma16816(o[dn], pl, bvh2);
            }

            // Commit prefetched next tile halfway through this tile's compute
            if (nc == 1 && pre) {
                __nv_bfloat16* kh = (__nv_bfloat16*)(blk[buf ^ 1] + KH_);
                __nv_bfloat16* kl = (__nv_bfloat16*)(blk[buf ^ 1] + KL_);
                __nv_bfloat16* vh = (__nv_bfloat16*)(blk[buf ^ 1] + VH_);
                __nv_bfloat16* vl = (__nv_bfloat16*)(blk[buf ^ 1] + VL_);
#pragma unroll
                for (int i = 0; i < 4; i++) {
                    int j = tid + THREADS_ * i;
                    int idx = (j >> 4) * ROWP_ + ((j & 15) << 2);
                    split_store4(kh, kl, idx, kr[i].x, kr[i].y, kr[i].z, kr[i].w);
                    split_store4(vh, vl, idx, vr[i].x, vr[i].y, vr[i].z, vr[i].w);
                }
                if (tid < KT_) ((float*)(blk[buf ^ 1] + MSK_))[tid] = mreg ? 1.f : 0.f;
            }
        }
        __syncthreads();
    }

    // ---- Rowsum reduce across the 4 lanes sharing each row; store 1/rowsum ----
    rs0 += __shfl_xor_sync(0xffffffffu, rs0, 1);
    rs0 += __shfl_xor_sync(0xffffffffu, rs0, 2);
    rs1 += __shfl_xor_sync(0xffffffffu, rs1, 1);
    rs1 += __shfl_xor_sync(0xffffffffu, rs1, 2);
    if ((lane & 3) == 0) {
        srs[wid * 16 + (lane >> 2)]     = 1.f / rs0;
        srs[wid * 16 + (lane >> 2) + 8] = 1.f / rs1;
    }
    __syncthreads();   // also makes all Ag writes CTA-visible

    // ---- Write output: o / rowsum ----
    {
        const float inv0 = srs[qr0];
        const float inv1 = srs[qr0 + 8];
#pragma unroll
        for (int dn = 0; dn < 8; dn++) {
            int col = dn * 8 + ((lane & 3) << 1);
            *reinterpret_cast<float2*>(Og + (size_t)qr0 * D_ + col) =
                make_float2(o[dn][0] * inv0, o[dn][1] * inv0);
            *reinterpret_cast<float2*>(Og + (size_t)(qr0 + 8) * D_ + col) =
                make_float2(o[dn][2] * inv1, o[dn][3] * inv1);
        }
    }

    // ---- Normalize sweep: attn tile (1MB) read, scale, streamed back ----
    {
        float4* A4 = reinterpret_cast<float4*>(Ag);
        constexpr int F4_PER_ROW = S_ / 4;              // 512
        constexpr int TOTAL_F4 = TQ_ * F4_PER_ROW;      // 65536
#pragma unroll 4
        for (int j = tid; j < TOTAL_F4; j += THREADS_) {
            int row = j >> 9;
            float inv = srs[row];
            float4 x = A4[j];
            x.x *= inv; x.y *= inv; x.z *= inv; x.w *= inv;
            __stwt(&A4[j], x);
        }
    }
}

} // namespace

extern "C" void kernel_launch(void* const* d_in, const int* in_sizes, int n_in,
                              void* d_out, int out_size) {
    (void)in_sizes; (void)n_in; (void)out_size;
    const float* q = (const float*)d_in[0];
    const float* k = (const float*)d_in[1];
    const float* v = (const float*)d_in[2];
    const int*   m = (const int*)d_in[3];
    float* out = (float*)d_out;

    cudaFuncSetAttribute(attn_kernel, cudaFuncAttributeMaxDynamicSharedMemorySize, SMEM_BYTES);
    dim3 grid(S_ / TQ_, BH_);   // x = q-tile fast-varying -> L2 K/V reuse within bh
    attn_kernel<<<grid, THREADS_, SMEM_BYTES>>>(q, k, v, m, out);
}

// round 5
// speedup vs baseline: 1.0612x; 1.0116x over previous
#include <cuda_runtime.h>
#include <cuda_bf16.h>
#include <cstdint>

// ============================================================================
// Fused SDPA with attn-matrix output — single compute pass + normalize sweep.
// R5: x4 ldmatrix (half the LDSM instruction count), nt/dn pair processing,
//     prefetch commit moved later & split (K at nc==2, V+mask at nc==3).
// (tcgen05 is unavailable: harness ptxas targets sm_103 without the 'a'.)
// ============================================================================

namespace {

constexpr int S_  = 2048;
constexpr int D_  = 64;
constexpr int BH_ = 32;          // B*H
constexpr int TQ_ = 128;         // queries per CTA
constexpr int KT_ = 64;          // keys per smem tile
constexpr int NKT_ = S_ / KT_;   // 32 key tiles
constexpr int THREADS_ = 256;    // 8 warps, warp w owns queries [16w,16w+16)
constexpr int ROWP_ = 72;        // padded bf16 row (144B): conflict-free LDSM

// smem layout (bytes)
constexpr int SQH_OFF = 0;
constexpr int SQL_OFF = SQH_OFF + TQ_ * ROWP_ * 2;        // 18432
constexpr int BUF_OFF = SQL_OFF + TQ_ * ROWP_ * 2;        // 36864
constexpr int KH_  = 0;
constexpr int KL_  = KH_ + KT_ * ROWP_ * 2;
constexpr int VH_  = KL_ + KT_ * ROWP_ * 2;
constexpr int VL_  = VH_ + KT_ * ROWP_ * 2;
constexpr int MSK_ = VL_ + KT_ * ROWP_ * 2;
constexpr int BLK_SZ = MSK_ + KT_ * 4;                    // 37120
constexpr int SRS_OFF = BUF_OFF + 2 * BLK_SZ;             // 111104
constexpr int SMEM_BYTES = SRS_OFF + TQ_ * 4;             // 111616

__device__ __forceinline__ uint32_t smem_u32(const void* p) {
    return (uint32_t)__cvta_generic_to_shared(p);
}
__device__ __forceinline__ void ldsm_x4(uint32_t a[4], uint32_t addr) {
    asm volatile("ldmatrix.sync.aligned.m8n8.x4.shared.b16 {%0,%1,%2,%3}, [%4];"
                 : "=r"(a[0]), "=r"(a[1]), "=r"(a[2]), "=r"(a[3]) : "r"(addr));
}
__device__ __forceinline__ void ldsm_x4t(uint32_t a[4], uint32_t addr) {
    asm volatile("ldmatrix.sync.aligned.m8n8.x4.trans.shared.b16 {%0,%1,%2,%3}, [%4];"
                 : "=r"(a[0]), "=r"(a[1]), "=r"(a[2]), "=r"(a[3]) : "r"(addr));
}
__device__ __forceinline__ void mma16816(float c[4], const uint32_t a[4], const uint32_t b[2]) {
    asm volatile(
        "mma.sync.aligned.m16n8k16.row.col.f32.bf16.bf16.f32 "
        "{%0,%1,%2,%3}, {%4,%5,%6,%7}, {%8,%9}, {%0,%1,%2,%3};"
        : "+f"(c[0]), "+f"(c[1]), "+f"(c[2]), "+f"(c[3])
        : "r"(a[0]), "r"(a[1]), "r"(a[2]), "r"(a[3]), "r"(b[0]), "r"(b[1]));
}
__device__ __forceinline__ uint32_t pack_bf16(__nv_bfloat16 lo, __nv_bfloat16 hi) {
    return ((uint32_t)__bfloat16_as_ushort(hi) << 16) | (uint32_t)__bfloat16_as_ushort(lo);
}
__device__ __forceinline__ void split2(float x, float y, uint32_t& hi, uint32_t& lo) {
    __nv_bfloat16 hx = __float2bfloat16(x);
    __nv_bfloat16 hy = __float2bfloat16(y);
    hi = pack_bf16(hx, hy);
    lo = pack_bf16(__float2bfloat16(x - __bfloat162float(hx)),
                   __float2bfloat16(y - __bfloat162float(hy)));
}
// Split 4 consecutive floats into hi/lo bf16 and store as one uint2 each.
__device__ __forceinline__ void split_store4(__nv_bfloat16* hb, __nv_bfloat16* lb,
                                             int idx, float v0, float v1, float v2, float v3) {
    __nv_bfloat16 h0 = __float2bfloat16(v0), h1 = __float2bfloat16(v1);
    __nv_bfloat16 h2 = __float2bfloat16(v2), h3 = __float2bfloat16(v3);
    *reinterpret_cast<uint2*>(hb + idx) =
        make_uint2(pack_bf16(h0, h1), pack_bf16(h2, h3));
    __nv_bfloat16 l0 = __float2bfloat16(v0 - __bfloat162float(h0));
    __nv_bfloat16 l1 = __float2bfloat16(v1 - __bfloat162float(h1));
    __nv_bfloat16 l2 = __float2bfloat16(v2 - __bfloat162float(h2));
    __nv_bfloat16 l3 = __float2bfloat16(v3 - __bfloat162float(h3));
    *reinterpret_cast<uint2*>(lb + idx) =
        make_uint2(pack_bf16(l0, l1), pack_bf16(l2, l3));
}

// QK for a 16-key pair (two 16x8 score tiles) using x4 LDSM.
// hi*hi into c0/c1 (short chains); cross terms into e0/e1.
__device__ __forceinline__ void qk_pair(float c0[4], float c1[4],
                                        const uint32_t aH[4][4], const uint32_t aL[4][4],
                                        uint32_t bah, uint32_t bal) {
    float e0[4] = {0.f, 0.f, 0.f, 0.f};
    float e1[4] = {0.f, 0.f, 0.f, 0.f};
#pragma unroll
    for (int ds = 0; ds < 4; ds++) {
        uint32_t bh4[4], bl4[4];
        ldsm_x4(bh4, bah + ds * 32);   // keys n..n+15, d-chunk ds (hi)
        ldsm_x4(bl4, bal + ds * 32);   // (lo)
        mma16816(c0, aH[ds], bh4);
        mma16816(c1, aH[ds], bh4 + 2);
        mma16816(e0, aH[ds], bl4);
        mma16816(e1, aH[ds], bl4 + 2);
        mma16816(e0, aL[ds], bh4);
        mma16816(e1, aL[ds], bh4 + 2);
    }
#pragma unroll
    for (int i = 0; i < 4; i++) { c0[i] += e0[i]; c1[i] += e1[i]; }
}

__global__ void __launch_bounds__(THREADS_, 2)
attn_kernel(const float* __restrict__ Q, const float* __restrict__ K,
            const float* __restrict__ V, const int* __restrict__ M,
            float* __restrict__ Out) {
    extern __shared__ char smem[];
    __nv_bfloat16* sQh = (__nv_bfloat16*)(smem + SQH_OFF);
    __nv_bfloat16* sQl = (__nv_bfloat16*)(smem + SQL_OFF);
    float* srs = (float*)(smem + SRS_OFF);
    char* blk[2] = {smem + BUF_OFF, smem + BUF_OFF + BLK_SZ};

    const int qt = blockIdx.x;
    const int bh = blockIdx.y;
    const int tid = threadIdx.x;
    const int wid = tid >> 5;
    const int lane = tid & 31;
    const int b = bh >> 4;  // H = 16

    const size_t base = (size_t)bh * S_ * D_;
    const float* Qg = Q + base + (size_t)qt * TQ_ * D_;
    const float* Kg = K + base;
    const float* Vg = V + base;
    const int*   Mg = M + (size_t)b * S_;
    float* Og = Out + base + (size_t)qt * TQ_ * D_;
    float* Ag = Out + (size_t)BH_ * S_ * D_ + (size_t)bh * S_ * S_ + (size_t)qt * TQ_ * S_;

    // ---- Load Q tile, scale by 1/temperature, bf16 hi/lo split into smem ----
#pragma unroll
    for (int i = 0; i < 8; i++) {
        int j = tid + THREADS_ * i;                 // float4 index, 2048 total
        float4 x = reinterpret_cast<const float4*>(Qg)[j];
        int idx = (j >> 4) * ROWP_ + ((j & 15) << 2);
        split_store4(sQh, sQl, idx, x.x * 0.125f, x.y * 0.125f, x.z * 0.125f, x.w * 0.125f);
    }
    __syncthreads();

    // ---- Persistent A fragments (this warp's 16 queries, full D=64) ----
    uint32_t aH[4][4], aL[4][4];
    {
        int r = wid * 16 + (lane & 15);
        int ch = (lane >> 4) * 8;
#pragma unroll
        for (int ds = 0; ds < 4; ds++) {
            ldsm_x4(aH[ds], smem_u32(&sQh[r * ROWP_ + ds * 16 + ch]));
            ldsm_x4(aL[ds], smem_u32(&sQl[r * ROWP_ + ds * 16 + ch]));
        }
    }

    // x4 LDSM base addresses.
    // K (non-trans): lanes 0-7 rows k0-7 (d-lo 16B), 8-15 same rows d-hi,
    //                16-23 rows k8-15 d-lo, 24-31 rows k8-15 d-hi.
    // V (trans):     lanes 0-15 rows k0-15 at d-chunk dn, 16-31 at dn+1.
    uint32_t bkh[2], bkl[2], bvh[2], bvl[2];
#pragma unroll
    for (int u = 0; u < 2; u++) {
        uint32_t koff = (((lane & 7) + ((lane >> 4) << 3)) * ROWP_) * 2 + ((lane >> 3) & 1) * 16;
        uint32_t voff = (lane & 15) * ROWP_ * 2 + (lane >> 4) * 16;
        bkh[u] = smem_u32(blk[u] + KH_) + koff;
        bkl[u] = smem_u32(blk[u] + KL_) + koff;
        bvh[u] = smem_u32(blk[u] + VH_) + voff;
        bvl[u] = smem_u32(blk[u] + VL_) + voff;
    }
    const int rsb = ROWP_ * 2;   // bytes per smem row
    const int qr0 = wid * 16 + (lane >> 2);

    float rs0 = 0.f, rs1 = 0.f;
    float o[8][4];
#pragma unroll
    for (int dn = 0; dn < 8; dn++)
#pragma unroll
        for (int c = 0; c < 4; c++) o[dn][c] = 0.f;

    // ---- Preload tile 0 (K + V + mask) into buf 0 ----
    {
        float4 kr[4], vr[4];
#pragma unroll
        for (int i = 0; i < 4; i++) {
            kr[i] = reinterpret_cast<const float4*>(Kg)[tid + THREADS_ * i];
            vr[i] = reinterpret_cast<const float4*>(Vg)[tid + THREADS_ * i];
        }
        __nv_bfloat16* kh = (__nv_bfloat16*)(blk[0] + KH_);
        __nv_bfloat16* kl = (__nv_bfloat16*)(blk[0] + KL_);
        __nv_bfloat16* vh = (__nv_bfloat16*)(blk[0] + VH_);
        __nv_bfloat16* vl = (__nv_bfloat16*)(blk[0] + VL_);
#pragma unroll
        for (int i = 0; i < 4; i++) {
            int j = tid + THREADS_ * i;
            int idx = (j >> 4) * ROWP_ + ((j & 15) << 2);
            split_store4(kh, kl, idx, kr[i].x, kr[i].y, kr[i].z, kr[i].w);
            split_store4(vh, vl, idx, vr[i].x, vr[i].y, vr[i].z, vr[i].w);
        }
        if (tid < KT_) ((float*)(blk[0] + MSK_))[tid] = Mg[tid] ? 1.f : 0.f;
    }
    __syncthreads();

    // ======================= Single compute pass =======================
#pragma unroll 1
    for (int kt = 0; kt < NKT_; kt++) {
        const int buf = kt & 1;
        const float* msk = (const float*)(blk[buf] + MSK_);
        const bool pre = (kt + 1 < NKT_);

        float4 kr[4], vr[4];
        int mreg = 0;
        if (pre) {
            const float4* nk = reinterpret_cast<const float4*>(Kg + (size_t)(kt + 1) * KT_ * D_);
            const float4* nv = reinterpret_cast<const float4*>(Vg + (size_t)(kt + 1) * KT_ * D_);
#pragma unroll
            for (int i = 0; i < 4; i++) { kr[i] = nk[tid + THREADS_ * i]; vr[i] = nv[tid + THREADS_ * i]; }
            if (tid < KT_) mreg = Mg[(kt + 1) * KT_ + tid];
        }

#pragma unroll
        for (int nc = 0; nc < 4; nc++) {            // 16-key chunks
            const int n0 = nc * 16;
            float pn[2][4];
            {
                float c0[4] = {0.f, 0.f, 0.f, 0.f};
                float c1[4] = {0.f, 0.f, 0.f, 0.f};
                qk_pair(c0, c1, aH, aL, bkh[buf] + n0 * rsb, bkl[buf] + n0 * rsb);
                int kc = n0 + ((lane & 3) << 1);
                float m00 = msk[kc],     m01 = msk[kc + 1];
                float m10 = msk[kc + 8], m11 = msk[kc + 9];
                pn[0][0] = m00 * __expf(c0[0]);
                pn[0][1] = m01 * __expf(c0[1]);
                pn[0][2] = m00 * __expf(c0[2]);
                pn[0][3] = m01 * __expf(c0[3]);
                pn[1][0] = m10 * __expf(c1[0]);
                pn[1][1] = m11 * __expf(c1[1]);
                pn[1][2] = m10 * __expf(c1[2]);
                pn[1][3] = m11 * __expf(c1[3]);
                rs0 += pn[0][0] + pn[0][1] + pn[1][0] + pn[1][1];
                rs1 += pn[0][2] + pn[0][3] + pn[1][2] + pn[1][3];
            }

            // Write UNNORMALIZED p (regular stores -> L2-resident for readback)
#pragma unroll
            for (int nt = 0; nt < 2; nt++) {
                int col = kt * KT_ + n0 + nt * 8 + ((lane & 3) << 1);
                *reinterpret_cast<float2*>(Ag + (size_t)qr0 * S_ + col) =
                    make_float2(pn[nt][0], pn[nt][1]);
                *reinterpret_cast<float2*>(Ag + (size_t)(qr0 + 8) * S_ + col) =
                    make_float2(pn[nt][2], pn[nt][3]);
            }

            // Repack C-fragments directly as A-fragments for PV
            uint32_t ph[4], pl[4];
            split2(pn[0][0], pn[0][1], ph[0], pl[0]);
            split2(pn[0][2], pn[0][3], ph[1], pl[1]);
            split2(pn[1][0], pn[1][1], ph[2], pl[2]);
            split2(pn[1][2], pn[1][3], ph[3], pl[3]);

            const uint32_t vah = bvh[buf] + n0 * rsb;
            const uint32_t val_ = bvl[buf] + n0 * rsb;
#pragma unroll
            for (int dp = 0; dp < 4; dp++) {        // dn pairs
                uint32_t vh4[4], vl4[4];
                ldsm_x4t(vh4, vah + dp * 32);
                ldsm_x4t(vl4, val_ + dp * 32);
                mma16816(o[2 * dp],     ph, vh4);
                mma16816(o[2 * dp],     ph, vl4);
                mma16816(o[2 * dp],     pl, vh4);
                mma16816(o[2 * dp + 1], ph, vh4 + 2);
                mma16816(o[2 * dp + 1], ph, vl4 + 2);
                mma16816(o[2 * dp + 1], pl, vh4 + 2);
            }

            // Commit prefetched tile late, split across chunks:
            //   K at nc==2, V + mask at nc==3 (max LDG slack, spread STS).
            if (nc == 2 && pre) {
                __nv_bfloat16* kh = (__nv_bfloat16*)(blk[buf ^ 1] + KH_);
                __nv_bfloat16* kl = (__nv_bfloat16*)(blk[buf ^ 1] + KL_);
#pragma unroll
                for (int i = 0; i < 4; i++) {
                    int j = tid + THREADS_ * i;
                    int idx = (j >> 4) * ROWP_ + ((j & 15) << 2);
                    split_store4(kh, kl, idx, kr[i].x, kr[i].y, kr[i].z, kr[i].w);
                }
            }
            if (nc == 3 && pre) {
                __nv_bfloat16* vh = (__nv_bfloat16*)(blk[buf ^ 1] + VH_);
                __nv_bfloat16* vl = (__nv_bfloat16*)(blk[buf ^ 1] + VL_);
#pragma unroll
                for (int i = 0; i < 4; i++) {
                    int j = tid + THREADS_ * i;
                    int idx = (j >> 4) * ROWP_ + ((j & 15) << 2);
                    split_store4(vh, vl, idx, vr[i].x, vr[i].y, vr[i].z, vr[i].w);
                }
                if (tid < KT_) ((float*)(blk[buf ^ 1] + MSK_))[tid] = mreg ? 1.f : 0.f;
            }
        }
        __syncthreads();
    }

    // ---- Rowsum reduce across the 4 lanes sharing each row; store 1/rowsum ----
    rs0 += __shfl_xor_sync(0xffffffffu, rs0, 1);
    rs0 += __shfl_xor_sync(0xffffffffu, rs0, 2);
    rs1 += __shfl_xor_sync(0xffffffffu, rs1, 1);
    rs1 += __shfl_xor_sync(0xffffffffu, rs1, 2);
    if ((lane & 3) == 0) {
        srs[wid * 16 + (lane >> 2)]     = 1.f / rs0;
        srs[wid * 16 + (lane >> 2) + 8] = 1.f / rs1;
    }
    __syncthreads();   // also makes all Ag writes CTA-visible

    // ---- Write output: o / rowsum ----
    {
        const float inv0 = srs[qr0];
        const float inv1 = srs[qr0 + 8];
#pragma unroll
        for (int dn = 0; dn < 8; dn++) {
            int col = dn * 8 + ((lane & 3) << 1);
            *reinterpret_cast<float2*>(Og + (size_t)qr0 * D_ + col) =
                make_float2(o[dn][0] * inv0, o[dn][1] * inv0);
            *reinterpret_cast<float2*>(Og + (size_t)(qr0 + 8) * D_ + col) =
                make_float2(o[dn][2] * inv1, o[dn][3] * inv1);
        }
    }

    // ---- Normalize sweep: attn tile (1MB) read, scale, streamed back ----
    {
        float4* A4 = reinterpret_cast<float4*>(Ag);
        constexpr int F4_PER_ROW = S_ / 4;              // 512
        constexpr int TOTAL_F4 = TQ_ * F4_PER_ROW;      // 65536
#pragma unroll 4
        for (int j = tid; j < TOTAL_F4; j += THREADS_) {
            int row = j >> 9;
            float inv = srs[row];
            float4 x = A4[j];
            x.x *= inv; x.y *= inv; x.z *= inv; x.w *= inv;
            __stwt(&A4[j], x);
        }
    }
}

} // namespace

extern "C" void kernel_launch(void* const* d_in, const int* in_sizes, int n_in,
                              void* d_out, int out_size) {
    (void)in_sizes; (void)n_in; (void)out_size;
    const float* q = (const float*)d_in[0];
    const float* k = (const float*)d_in[1];
    const float* v = (const float*)d_in[2];
    const int*   m = (const int*)d_in[3];
    float* out = (float*)d_out;

    cudaFuncSetAttribute(attn_kernel, cudaFuncAttributeMaxDynamicSharedMemorySize, SMEM_BYTES);
    dim3 grid(S_ / TQ_, BH_);   // x = q-tile fast-varying -> L2 K/V reuse within bh
    attn_kernel<<<grid, THREADS_, SMEM_BYTES>>>(q, k, v, m, out);
}

// round 6
// speedup vs baseline: 1.2189x; 1.1486x over previous
#include <cuda_runtime.h>
#include <cuda_bf16.h>
#include <cstdint>

// ============================================================================
// Fused SDPA with attn-matrix output.
// R6: two kernels.
//   convert_kernel: Q(/8),K,V -> bf16 hi/lo scratch (__device__), mask -> float.
//   attn_kernel:    cp.async 2-stage K/V pipeline (no in-loop conversion),
//                   QK 3-split mma -> p=mask*exp (unnormalized attn out, rowsum)
//                   -> PV 3-split mma; tail: out=acc/rowsum + normalize sweep.
// ============================================================================

namespace {

constexpr int S_  = 2048;
constexpr int D_  = 64;
constexpr int BH_ = 32;          // B*H
constexpr int TQ_ = 128;         // queries per CTA
constexpr int KT_ = 64;          // keys per stage
constexpr int NKT_ = S_ / KT_;   // 32 tiles
constexpr int THREADS_ = 256;    // 8 warps
constexpr int ROWP_ = 72;        // padded bf16 row (144B) -> conflict-free LDSM
constexpr int NELEM_ = BH_ * S_ * D_;   // 4.19M per tensor

// ---- bf16 hi/lo scratch (dense 64-elem rows) ----
__device__ __nv_bfloat16 g_qh[NELEM_], g_ql[NELEM_];
__device__ __nv_bfloat16 g_kh[NELEM_], g_kl[NELEM_];
__device__ __nv_bfloat16 g_vh[NELEM_], g_vl[NELEM_];
__device__ float g_mf[2 * S_];

// ---- smem layout (bytes) ----
constexpr int SQH_OFF = 0;
constexpr int SQL_OFF = SQH_OFF + TQ_ * ROWP_ * 2;   // 18432
constexpr int STAGE_OFF = SQL_OFF + TQ_ * ROWP_ * 2; // 36864
constexpr int KH_  = 0;
constexpr int KL_  = KH_ + KT_ * ROWP_ * 2;          // 9216
constexpr int VH_  = KL_ + KT_ * ROWP_ * 2;          // 18432
constexpr int VL_  = VH_ + KT_ * ROWP_ * 2;          // 27648
constexpr int MSK_ = VL_ + KT_ * ROWP_ * 2;          // 36864 (within stage)
constexpr int STG_SZ = MSK_ + KT_ * 4;               // 37120
constexpr int SRS_OFF = STAGE_OFF + 2 * STG_SZ;      // 111104
constexpr int SMEM_BYTES = SRS_OFF + TQ_ * 4;        // 111616

__device__ __forceinline__ uint32_t smem_u32(const void* p) {
    return (uint32_t)__cvta_generic_to_shared(p);
}
__device__ __forceinline__ void cp16(uint32_t dst, const void* src) {
    asm volatile("cp.async.cg.shared.global [%0], [%1], 16;" :: "r"(dst), "l"(src));
}
#define CP_COMMIT() asm volatile("cp.async.commit_group;" ::: "memory")
#define CP_WAIT(n)  asm volatile("cp.async.wait_group %0;" :: "n"(n) : "memory")

__device__ __forceinline__ void ldsm_x4(uint32_t a[4], uint32_t addr) {
    asm volatile("ldmatrix.sync.aligned.m8n8.x4.shared.b16 {%0,%1,%2,%3}, [%4];"
                 : "=r"(a[0]), "=r"(a[1]), "=r"(a[2]), "=r"(a[3]) : "r"(addr));
}
__device__ __forceinline__ void ldsm_x4t(uint32_t a[4], uint32_t addr) {
    asm volatile("ldmatrix.sync.aligned.m8n8.x4.trans.shared.b16 {%0,%1,%2,%3}, [%4];"
                 : "=r"(a[0]), "=r"(a[1]), "=r"(a[2]), "=r"(a[3]) : "r"(addr));
}
__device__ __forceinline__ void mma16816(float c[4], const uint32_t a[4], const uint32_t b[2]) {
    asm volatile(
        "mma.sync.aligned.m16n8k16.row.col.f32.bf16.bf16.f32 "
        "{%0,%1,%2,%3}, {%4,%5,%6,%7}, {%8,%9}, {%0,%1,%2,%3};"
        : "+f"(c[0]), "+f"(c[1]), "+f"(c[2]), "+f"(c[3])
        : "r"(a[0]), "r"(a[1]), "r"(a[2]), "r"(a[3]), "r"(b[0]), "r"(b[1]));
}
__device__ __forceinline__ uint32_t pack_bf16(__nv_bfloat16 lo, __nv_bfloat16 hi) {
    return ((uint32_t)__bfloat16_as_ushort(hi) << 16) | (uint32_t)__bfloat16_as_ushort(lo);
}
__device__ __forceinline__ void split2(float x, float y, uint32_t& hi, uint32_t& lo) {
    __nv_bfloat16 hx = __float2bfloat16(x);
    __nv_bfloat16 hy = __float2bfloat16(y);
    hi = pack_bf16(hx, hy);
    lo = pack_bf16(__float2bfloat16(x - __bfloat162float(hx)),
                   __float2bfloat16(y - __bfloat162float(hy)));
}
__device__ __forceinline__ void split4_u2(float4 v, uint2& h, uint2& l) {
    uint32_t h0, l0, h1, l1;
    split2(v.x, v.y, h0, l0);
    split2(v.z, v.w, h1, l1);
    h = make_uint2(h0, h1);
    l = make_uint2(l0, l1);
}

// ---------------------------------------------------------------------------
__global__ void __launch_bounds__(256)
convert_kernel(const float* __restrict__ q, const float* __restrict__ k,
               const float* __restrict__ v, const int* __restrict__ m) {
    const int N4 = NELEM_ / 4;
    const int stride = gridDim.x * blockDim.x;
    for (int j = blockIdx.x * blockDim.x + threadIdx.x; j < N4; j += stride) {
        float4 x = reinterpret_cast<const float4*>(q)[j];
        x.x *= 0.125f; x.y *= 0.125f; x.z *= 0.125f; x.w *= 0.125f;
        uint2 h, l;
        split4_u2(x, h, l);
        reinterpret_cast<uint2*>(g_qh)[j] = h;
        reinterpret_cast<uint2*>(g_ql)[j] = l;
        split4_u2(reinterpret_cast<const float4*>(k)[j], h, l);
        reinterpret_cast<uint2*>(g_kh)[j] = h;
        reinterpret_cast<uint2*>(g_kl)[j] = l;
        split4_u2(reinterpret_cast<const float4*>(v)[j], h, l);
        reinterpret_cast<uint2*>(g_vh)[j] = h;
        reinterpret_cast<uint2*>(g_vl)[j] = l;
    }
    for (int j = blockIdx.x * blockDim.x + threadIdx.x; j < 2 * S_; j += stride)
        g_mf[j] = m[j] ? 1.f : 0.f;
}

// Issue one K/V stage (2048 x 16B chunks) + mask (16 chunks) via cp.async.
__device__ __forceinline__ void cp_tile_kv(uint32_t stg, size_t kvoff,
                                           size_t moff, int tid) {
#pragma unroll
    for (int i = 0; i < 2; i++) {
        int c = tid + THREADS_ * i;                 // 0..511
        int row = c >> 3, j = c & 7;
        uint32_t so = row * 144 + j * 16;
        size_t go = kvoff + row * 64 + j * 8;
        cp16(stg + KH_ + so, g_kh + go);
        cp16(stg + KL_ + so, g_kl + go);
        cp16(stg + VH_ + so, g_vh + go);
        cp16(stg + VL_ + so, g_vl + go);
    }
    if (tid < 16) cp16(stg + MSK_ + tid * 16, g_mf + moff + tid * 4);
}

// ---------------------------------------------------------------------------
__global__ void __launch_bounds__(THREADS_, 2)
attn_kernel(float* __restrict__ Out) {
    extern __shared__ char smem[];
    const uint32_t sb = smem_u32(smem);
    float* srs = (float*)(smem + SRS_OFF);

    const int qt = blockIdx.x;
    const int bh = blockIdx.y;
    const int tid = threadIdx.x;
    const int wid = tid >> 5;
    const int lane = tid & 31;
    const int b = bh >> 4;  // H = 16

    const size_t base = (size_t)bh * S_ * D_;
    const size_t qoff = base + (size_t)qt * TQ_ * D_;
    float* Og = Out + qoff;
    float* Ag = Out + (size_t)BH_ * S_ * D_ + (size_t)bh * S_ * S_ + (size_t)qt * TQ_ * S_;

    const uint32_t stg[2] = {sb + STAGE_OFF, sb + STAGE_OFF + STG_SZ};

    // ---- Prologue: async-load Q (group 0), tiles 0,1 (groups 1,2) ----
    {
#pragma unroll
        for (int i = 0; i < 4; i++) {
            int c = tid + THREADS_ * i;             // 0..1023
            int row = c >> 3, j = c & 7;
            uint32_t so = row * 144 + j * 16;
            size_t go = qoff + row * 64 + j * 8;
            cp16(sb + SQH_OFF + so, g_qh + go);
            cp16(sb + SQL_OFF + so, g_ql + go);
        }
        CP_COMMIT();
        cp_tile_kv(stg[0], base, (size_t)b * S_, tid);
        CP_COMMIT();
        cp_tile_kv(stg[1], base + KT_ * D_, (size_t)b * S_ + KT_, tid);
        CP_COMMIT();
    }
    CP_WAIT(2);
    __syncthreads();

    // ---- Persistent Q fragments (warp's 16 queries, full D=64) ----
    uint32_t aH[4][4], aL[4][4];
    {
        int r = wid * 16 + (lane & 15);
        int ch = (lane >> 4) * 8;
        const __nv_bfloat16* sQh = (const __nv_bfloat16*)(smem + SQH_OFF);
        const __nv_bfloat16* sQl = (const __nv_bfloat16*)(smem + SQL_OFF);
#pragma unroll
        for (int ds = 0; ds < 4; ds++) {
            ldsm_x4(aH[ds], smem_u32(&sQh[r * ROWP_ + ds * 16 + ch]));
            ldsm_x4(aL[ds], smem_u32(&sQl[r * ROWP_ + ds * 16 + ch]));
        }
    }

    // x4 LDSM base offsets (within a stage).
    const uint32_t koff = (((lane & 7) + ((lane >> 4) << 3)) * ROWP_) * 2 + ((lane >> 3) & 1) * 16;
    const uint32_t voff = (lane & 15) * ROWP_ * 2 + (lane >> 4) * 16;
    const int rsb = ROWP_ * 2;
    const int qr0 = wid * 16 + (lane >> 2);

    float rs0 = 0.f, rs1 = 0.f;
    float o[8][4];
#pragma unroll
    for (int dn = 0; dn < 8; dn++)
#pragma unroll
        for (int c = 0; c < 4; c++) o[dn][c] = 0.f;

    // ======================= Main loop =======================
#pragma unroll 1
    for (int kt = 0; kt < NKT_; kt++) {
        const int s = kt & 1;
        const uint32_t bkh = stg[s] + KH_ + koff;
        const uint32_t bkl = stg[s] + KL_ + koff;
        const uint32_t bvh = stg[s] + VH_ + voff;
        const uint32_t bvl = stg[s] + VL_ + voff;
        const float* msk = (const float*)(smem + STAGE_OFF + s * STG_SZ + MSK_);

        CP_WAIT(1);          // stage s data arrived (stage s^1 may still fly)
        __syncthreads();

#pragma unroll
        for (int nc = 0; nc < 4; nc++) {            // 16-key chunks
            const int n0 = nc * 16;
            float pn[2][4];
            {
                float c0[4] = {0.f, 0.f, 0.f, 0.f};
                float c1[4] = {0.f, 0.f, 0.f, 0.f};
                float e0[4] = {0.f, 0.f, 0.f, 0.f};
                float e1[4] = {0.f, 0.f, 0.f, 0.f};
#pragma unroll
                for (int ds = 0; ds < 4; ds++) {
                    uint32_t bh4[4], bl4[4];
                    ldsm_x4(bh4, bkh + n0 * rsb + ds * 32);
                    ldsm_x4(bl4, bkl + n0 * rsb + ds * 32);
                    mma16816(c0, aH[ds], bh4);
                    mma16816(c1, aH[ds], bh4 + 2);
                    mma16816(e0, aH[ds], bl4);
                    mma16816(e1, aH[ds], bl4 + 2);
                    mma16816(e0, aL[ds], bh4);
                    mma16816(e1, aL[ds], bh4 + 2);
                }
                int kc = n0 + ((lane & 3) << 1);
                float m00 = msk[kc],     m01 = msk[kc + 1];
                float m10 = msk[kc + 8], m11 = msk[kc + 9];
                pn[0][0] = m00 * __expf(c0[0] + e0[0]);
                pn[0][1] = m01 * __expf(c0[1] + e0[1]);
                pn[0][2] = m00 * __expf(c0[2] + e0[2]);
                pn[0][3] = m01 * __expf(c0[3] + e0[3]);
                pn[1][0] = m10 * __expf(c1[0] + e1[0]);
                pn[1][1] = m11 * __expf(c1[1] + e1[1]);
                pn[1][2] = m10 * __expf(c1[2] + e1[2]);
                pn[1][3] = m11 * __expf(c1[3] + e1[3]);
                rs0 += pn[0][0] + pn[0][1] + pn[1][0] + pn[1][1];
                rs1 += pn[0][2] + pn[0][3] + pn[1][2] + pn[1][3];
            }

            // Write UNNORMALIZED p (stays L2-resident for the sweep)
#pragma unroll
            for (int nt = 0; nt < 2; nt++) {
                int col = kt * KT_ + n0 + nt * 8 + ((lane & 3) << 1);
                *reinterpret_cast<float2*>(Ag + (size_t)qr0 * S_ + col) =
                    make_float2(pn[nt][0], pn[nt][1]);
                *reinterpret_cast<float2*>(Ag + (size_t)(qr0 + 8) * S_ + col) =
                    make_float2(pn[nt][2], pn[nt][3]);
            }

            // Repack C-fragments directly as A-fragments for PV
            uint32_t ph[4], pl[4];
            split2(pn[0][0], pn[0][1], ph[0], pl[0]);
            split2(pn[0][2], pn[0][3], ph[1], pl[1]);
            split2(pn[1][0], pn[1][1], ph[2], pl[2]);
            split2(pn[1][2], pn[1][3], ph[3], pl[3]);

#pragma unroll
            for (int dp = 0; dp < 4; dp++) {        // dn pairs
                uint32_t vh4[4], vl4[4];
                ldsm_x4t(vh4, bvh + n0 * rsb + dp * 32);
                ldsm_x4t(vl4, bvl + n0 * rsb + dp * 32);
                mma16816(o[2 * dp],     ph, vh4);
                mma16816(o[2 * dp],     ph, vl4);
                mma16816(o[2 * dp],     pl, vh4);
                mma16816(o[2 * dp + 1], ph, vh4 + 2);
                mma16816(o[2 * dp + 1], ph, vl4 + 2);
                mma16816(o[2 * dp + 1], pl, vh4 + 2);
            }
        }

        __syncthreads();    // all warps done reading stage s
        if (kt + 2 < NKT_)
            cp_tile_kv(stg[s], base + (size_t)(kt + 2) * KT_ * D_,
                       (size_t)b * S_ + (kt + 2) * KT_, tid);
        CP_COMMIT();        // keep group accounting aligned (may be empty)
    }

    // ---- Rowsum reduce across the 4 lanes sharing each row; store 1/rowsum ----
    rs0 += __shfl_xor_sync(0xffffffffu, rs0, 1);
    rs0 += __shfl_xor_sync(0xffffffffu, rs0, 2);
    rs1 += __shfl_xor_sync(0xffffffffu, rs1, 1);
    rs1 += __shfl_xor_sync(0xffffffffu, rs1, 2);
    if ((lane & 3) == 0) {
        srs[wid * 16 + (lane >> 2)]     = 1.f / rs0;
        srs[wid * 16 + (lane >> 2) + 8] = 1.f / rs1;
    }
    __syncthreads();   // also makes all Ag writes CTA-visible

    // ---- Write output: o / rowsum ----
    {
        const float inv0 = srs[qr0];
        const float inv1 = srs[qr0 + 8];
#pragma unroll
        for (int dn = 0; dn < 8; dn++) {
            int col = dn * 8 + ((lane & 3) << 1);
            *reinterpret_cast<float2*>(Og + (size_t)qr0 * D_ + col) =
                make_float2(o[dn][0] * inv0, o[dn][1] * inv0);
            *reinterpret_cast<float2*>(Og + (size_t)(qr0 + 8) * D_ + col) =
                make_float2(o[dn][2] * inv1, o[dn][3] * inv1);
        }
    }

    // ---- Normalize sweep: attn tile (1MB) read, scale, streamed back ----
    {
        float4* A4 = reinterpret_cast<float4*>(Ag);
        constexpr int TOTAL_F4 = TQ_ * (S_ / 4);   // 65536
#pragma unroll 4
        for (int j = tid; j < TOTAL_F4; j += THREADS_) {
            int row = j >> 9;
            float inv = srs[row];
            float4 x = A4[j];
            x.x *= inv; x.y *= inv; x.z *= inv; x.w *= inv;
            __stwt(&A4[j], x);
        }
    }
}

} // namespace

extern "C" void kernel_launch(void* const* d_in, const int* in_sizes, int n_in,
                              void* d_out, int out_size) {
    (void)in_sizes; (void)n_in; (void)out_size;
    const float* q = (const float*)d_in[0];
    const float* k = (const float*)d_in[1];
    const float* v = (const float*)d_in[2];
    const int*   m = (const int*)d_in[3];
    float* out = (float*)d_out;

    convert_kernel<<<2048, 256>>>(q, k, v, m);

    cudaFuncSetAttribute(attn_kernel, cudaFuncAttributeMaxDynamicSharedMemorySize, SMEM_BYTES);
    dim3 grid(S_ / TQ_, BH_);   // x = q-tile fast-varying -> L2 K/V reuse within bh
    attn_kernel<<<grid, THREADS_, SMEM_BYTES>>>(out);
}

// round 7
// speedup vs baseline: 1.2804x; 1.0505x over previous
#include <cuda_runtime.h>
#include <cuda_bf16.h>
#include <cstdint>

// ============================================================================
// Fused SDPA with attn-matrix output.
// R7: 3-stage cp.async pipeline with ONE __syncthreads per tile (prefetch
//     issued at top, provably-free stage), Q smem overlaid on stage 2,
//     PV mma issued before attn stores.
//   convert_kernel: Q(/8),K,V -> bf16 hi/lo scratch, mask -> float.
//   attn_kernel:    QK 3-split mma -> p=mask*exp (unnormalized attn, rowsum)
//                   -> PV 3-split mma; tail: out=acc/rowsum + normalize sweep.
// ============================================================================

namespace {

constexpr int S_  = 2048;
constexpr int D_  = 64;
constexpr int BH_ = 32;          // B*H
constexpr int TQ_ = 128;         // queries per CTA
constexpr int KT_ = 64;          // keys per stage
constexpr int NKT_ = S_ / KT_;   // 32 tiles
constexpr int THREADS_ = 256;    // 8 warps
constexpr int ROWP_ = 72;        // padded bf16 row (144B) -> conflict-free LDSM
constexpr int NELEM_ = BH_ * S_ * D_;   // 4.19M per tensor

// ---- bf16 hi/lo scratch (dense 64-elem rows) ----
__device__ __nv_bfloat16 g_qh[NELEM_], g_ql[NELEM_];
__device__ __nv_bfloat16 g_kh[NELEM_], g_kl[NELEM_];
__device__ __nv_bfloat16 g_vh[NELEM_], g_vl[NELEM_];
__device__ float g_mf[2 * S_];

// ---- smem layout (bytes): 3 stages; Q overlays stage 2 ----
constexpr int KH_  = 0;
constexpr int KL_  = KH_ + KT_ * ROWP_ * 2;          // 9216
constexpr int VH_  = KL_ + KT_ * ROWP_ * 2;          // 18432
constexpr int VL_  = VH_ + KT_ * ROWP_ * 2;          // 27648
constexpr int MSK_ = VL_ + KT_ * ROWP_ * 2;          // 36864 (within stage)
constexpr int STG_SZ = MSK_ + KT_ * 4;               // 37120
constexpr int SQH_OFF = 2 * STG_SZ;                  // Q hi overlays stage 2
constexpr int SQL_OFF = SQH_OFF + TQ_ * ROWP_ / 2 * 2 * 2;  // +18432
constexpr int SRS_OFF = 3 * STG_SZ;                  // 111360
constexpr int SMEM_BYTES = SRS_OFF + TQ_ * 4;        // 111872

__device__ __forceinline__ uint32_t smem_u32(const void* p) {
    return (uint32_t)__cvta_generic_to_shared(p);
}
__device__ __forceinline__ void cp16(uint32_t dst, const void* src) {
    asm volatile("cp.async.cg.shared.global [%0], [%1], 16;" :: "r"(dst), "l"(src));
}
#define CP_COMMIT() asm volatile("cp.async.commit_group;" ::: "memory")
#define CP_WAIT(n)  asm volatile("cp.async.wait_group %0;" :: "n"(n) : "memory")

__device__ __forceinline__ void ldsm_x4(uint32_t a[4], uint32_t addr) {
    asm volatile("ldmatrix.sync.aligned.m8n8.x4.shared.b16 {%0,%1,%2,%3}, [%4];"
                 : "=r"(a[0]), "=r"(a[1]), "=r"(a[2]), "=r"(a[3]) : "r"(addr));
}
__device__ __forceinline__ void ldsm_x4t(uint32_t a[4], uint32_t addr) {
    asm volatile("ldmatrix.sync.aligned.m8n8.x4.trans.shared.b16 {%0,%1,%2,%3}, [%4];"
                 : "=r"(a[0]), "=r"(a[1]), "=r"(a[2]), "=r"(a[3]) : "r"(addr));
}
__device__ __forceinline__ void mma16816(float c[4], const uint32_t a[4], const uint32_t b[2]) {
    asm volatile(
        "mma.sync.aligned.m16n8k16.row.col.f32.bf16.bf16.f32 "
        "{%0,%1,%2,%3}, {%4,%5,%6,%7}, {%8,%9}, {%0,%1,%2,%3};"
        : "+f"(c[0]), "+f"(c[1]), "+f"(c[2]), "+f"(c[3])
        : "r"(a[0]), "r"(a[1]), "r"(a[2]), "r"(a[3]), "r"(b[0]), "r"(b[1]));
}
__device__ __forceinline__ uint32_t pack_bf16(__nv_bfloat16 lo, __nv_bfloat16 hi) {
    return ((uint32_t)__bfloat16_as_ushort(hi) << 16) | (uint32_t)__bfloat16_as_ushort(lo);
}
__device__ __forceinline__ void split2(float x, float y, uint32_t& hi, uint32_t& lo) {
    __nv_bfloat16 hx = __float2bfloat16(x);
    __nv_bfloat16 hy = __float2bfloat16(y);
    hi = pack_bf16(hx, hy);
    lo = pack_bf16(__float2bfloat16(x - __bfloat162float(hx)),
                   __float2bfloat16(y - __bfloat162float(hy)));
}
__device__ __forceinline__ void split4_u2(float4 v, uint2& h, uint2& l) {
    uint32_t h0, l0, h1, l1;
    split2(v.x, v.y, h0, l0);
    split2(v.z, v.w, h1, l1);
    h = make_uint2(h0, h1);
    l = make_uint2(l0, l1);
}

// ---------------------------------------------------------------------------
__global__ void __launch_bounds__(256)
convert_kernel(const float* __restrict__ q, const float* __restrict__ k,
               const float* __restrict__ v, const int* __restrict__ m) {
    const int N4 = NELEM_ / 4;
    const int stride = gridDim.x * blockDim.x;
    for (int j = blockIdx.x * blockDim.x + threadIdx.x; j < N4; j += stride) {
        float4 x = reinterpret_cast<const float4*>(q)[j];
        x.x *= 0.125f; x.y *= 0.125f; x.z *= 0.125f; x.w *= 0.125f;
        uint2 h, l;
        split4_u2(x, h, l);
        reinterpret_cast<uint2*>(g_qh)[j] = h;
        reinterpret_cast<uint2*>(g_ql)[j] = l;
        split4_u2(reinterpret_cast<const float4*>(k)[j], h, l);
        reinterpret_cast<uint2*>(g_kh)[j] = h;
        reinterpret_cast<uint2*>(g_kl)[j] = l;
        split4_u2(reinterpret_cast<const float4*>(v)[j], h, l);
        reinterpret_cast<uint2*>(g_vh)[j] = h;
        reinterpret_cast<uint2*>(g_vl)[j] = l;
    }
    for (int j = blockIdx.x * blockDim.x + threadIdx.x; j < 2 * S_; j += stride)
        g_mf[j] = m[j] ? 1.f : 0.f;
}

// Issue one K/V stage (2048 x 16B chunks) + mask (16 chunks) via cp.async.
__device__ __forceinline__ void cp_tile_kv(uint32_t stg, size_t kvoff,
                                           size_t moff, int tid) {
#pragma unroll
    for (int i = 0; i < 2; i++) {
        int c = tid + THREADS_ * i;                 // 0..511
        int row = c >> 3, j = c & 7;
        uint32_t so = row * 144 + j * 16;
        size_t go = kvoff + row * 64 + j * 8;
        cp16(stg + KH_ + so, g_kh + go);
        cp16(stg + KL_ + so, g_kl + go);
        cp16(stg + VH_ + so, g_vh + go);
        cp16(stg + VL_ + so, g_vl + go);
    }
    if (tid < 16) cp16(stg + MSK_ + tid * 16, g_mf + moff + tid * 4);
}

// ---------------------------------------------------------------------------
__global__ void __launch_bounds__(THREADS_, 2)
attn_kernel(float* __restrict__ Out) {
    extern __shared__ char smem[];
    const uint32_t sb = smem_u32(smem);
    float* srs = (float*)(smem + SRS_OFF);

    const int qt = blockIdx.x;
    const int bh = blockIdx.y;
    const int tid = threadIdx.x;
    const int wid = tid >> 5;
    const int lane = tid & 31;
    const int b = bh >> 4;  // H = 16

    const size_t base = (size_t)bh * S_ * D_;
    const size_t qoff = base + (size_t)qt * TQ_ * D_;
    const size_t moff = (size_t)b * S_;
    float* Og = Out + qoff;
    float* Ag = Out + (size_t)BH_ * S_ * D_ + (size_t)bh * S_ * S_ + (size_t)qt * TQ_ * S_;

    const uint32_t stg[3] = {sb, sb + STG_SZ, sb + 2 * STG_SZ};

    // ---- Prologue: cp Q (into stage-2 region), tiles 0 and 1 ----
    {
#pragma unroll
        for (int i = 0; i < 4; i++) {
            int c = tid + THREADS_ * i;             // 0..1023
            int row = c >> 3, j = c & 7;
            uint32_t so = row * 144 + j * 16;
            size_t go = qoff + row * 64 + j * 8;
            cp16(sb + SQH_OFF + so, g_qh + go);
            cp16(sb + SQL_OFF + so, g_ql + go);
        }
        CP_COMMIT();                                // group: Q
        cp_tile_kv(stg[0], base, moff, tid);
        CP_COMMIT();                                // group: tile 0
        cp_tile_kv(stg[1], base + KT_ * D_, moff + KT_, tid);
        CP_COMMIT();                                // group: tile 1
    }
    CP_WAIT(2);                                     // Q arrived
    __syncthreads();

    // ---- Persistent Q fragments (warp's 16 queries, full D=64) ----
    uint32_t aH[4][4], aL[4][4];
    {
        int r = wid * 16 + (lane & 15);
        int ch = (lane >> 4) * 8;
        const __nv_bfloat16* sQh = (const __nv_bfloat16*)(smem + SQH_OFF);
        const __nv_bfloat16* sQl = (const __nv_bfloat16*)(smem + SQL_OFF);
#pragma unroll
        for (int ds = 0; ds < 4; ds++) {
            ldsm_x4(aH[ds], smem_u32(&sQh[r * ROWP_ + ds * 16 + ch]));
            ldsm_x4(aL[ds], smem_u32(&sQl[r * ROWP_ + ds * 16 + ch]));
        }
    }
    __syncthreads();    // all warps done reading Q -> stage 2 region is free

    // x4 LDSM base offsets (within a stage).
    const uint32_t koff = (((lane & 7) + ((lane >> 4) << 3)) * ROWP_) * 2 + ((lane >> 3) & 1) * 16;
    const uint32_t voff = (lane & 15) * ROWP_ * 2 + (lane >> 4) * 16;
    const int rsb = ROWP_ * 2;
    const int qr0 = wid * 16 + (lane >> 2);

    float rs0 = 0.f, rs1 = 0.f;
    float o[8][4];
#pragma unroll
    for (int dn = 0; dn < 8; dn++)
#pragma unroll
        for (int c = 0; c < 4; c++) o[dn][c] = 0.f;

    // ======================= Main loop (ONE sync per tile) =======================
    int s = 0;          // stage holding tile kt
    int sp2 = 2;        // stage that tile kt+2 will go into (== stage of kt-1)
#pragma unroll 1
    for (int kt = 0; kt < NKT_; kt++) {
        CP_WAIT(1);          // this tile's data arrived (next may still fly)
        __syncthreads();     // all warps: visibility + stage sp2 retired

        // Prefetch tile kt+2 into the just-freed stage (overlaps compute below)
        if (kt + 2 < NKT_)
            cp_tile_kv(stg[sp2], base + (size_t)(kt + 2) * KT_ * D_,
                       moff + (kt + 2) * KT_, tid);
        CP_COMMIT();

        const uint32_t bkh = stg[s] + KH_ + koff;
        const uint32_t bkl = stg[s] + KL_ + koff;
        const uint32_t bvh = stg[s] + VH_ + voff;
        const uint32_t bvl = stg[s] + VL_ + voff;
        const float* msk = (const float*)(smem + (s * STG_SZ + MSK_));

#pragma unroll
        for (int nc = 0; nc < 4; nc++) {            // 16-key chunks
            const int n0 = nc * 16;
            float pn[2][4];
            {
                float c0[4] = {0.f, 0.f, 0.f, 0.f};
                float c1[4] = {0.f, 0.f, 0.f, 0.f};
                float e0[4] = {0.f, 0.f, 0.f, 0.f};
                float e1[4] = {0.f, 0.f, 0.f, 0.f};
#pragma unroll
                for (int ds = 0; ds < 4; ds++) {
                    uint32_t bh4[4], bl4[4];
                    ldsm_x4(bh4, bkh + n0 * rsb + ds * 32);
                    ldsm_x4(bl4, bkl + n0 * rsb + ds * 32);
                    mma16816(c0, aH[ds], bh4);
                    mma16816(c1, aH[ds], bh4 + 2);
                    mma16816(e0, aH[ds], bl4);
                    mma16816(e1, aH[ds], bl4 + 2);
                    mma16816(e0, aL[ds], bh4);
                    mma16816(e1, aL[ds], bh4 + 2);
                }
                int kc = n0 + ((lane & 3) << 1);
                float m00 = msk[kc],     m01 = msk[kc + 1];
                float m10 = msk[kc + 8], m11 = msk[kc + 9];
                pn[0][0] = m00 * __expf(c0[0] + e0[0]);
                pn[0][1] = m01 * __expf(c0[1] + e0[1]);
                pn[0][2] = m00 * __expf(c0[2] + e0[2]);
                pn[0][3] = m01 * __expf(c0[3] + e0[3]);
                pn[1][0] = m10 * __expf(c1[0] + e1[0]);
                pn[1][1] = m11 * __expf(c1[1] + e1[1]);
                pn[1][2] = m10 * __expf(c1[2] + e1[2]);
                pn[1][3] = m11 * __expf(c1[3] + e1[3]);
                rs0 += pn[0][0] + pn[0][1] + pn[1][0] + pn[1][1];
                rs1 += pn[0][2] + pn[0][3] + pn[1][2] + pn[1][3];
            }

            // Repack C-fragments directly as A-fragments for PV; issue mma first
            uint32_t ph[4], pl[4];
            split2(pn[0][0], pn[0][1], ph[0], pl[0]);
            split2(pn[0][2], pn[0][3], ph[1], pl[1]);
            split2(pn[1][0], pn[1][1], ph[2], pl[2]);
            split2(pn[1][2], pn[1][3], ph[3], pl[3]);

#pragma unroll
            for (int dp = 0; dp < 4; dp++) {        // dn pairs
                uint32_t vh4[4], vl4[4];
                ldsm_x4t(vh4, bvh + n0 * rsb + dp * 32);
                ldsm_x4t(vl4, bvl + n0 * rsb + dp * 32);
                mma16816(o[2 * dp],     ph, vh4);
                mma16816(o[2 * dp],     ph, vl4);
                mma16816(o[2 * dp],     pl, vh4);
                mma16816(o[2 * dp + 1], ph, vh4 + 2);
                mma16816(o[2 * dp + 1], ph, vl4 + 2);
                mma16816(o[2 * dp + 1], pl, vh4 + 2);
            }

            // Write UNNORMALIZED p after mma issue (stores are fire-and-forget)
#pragma unroll
            for (int nt = 0; nt < 2; nt++) {
                int col = kt * KT_ + n0 + nt * 8 + ((lane & 3) << 1);
                *reinterpret_cast<float2*>(Ag + (size_t)qr0 * S_ + col) =
                    make_float2(pn[nt][0], pn[nt][1]);
                *reinterpret_cast<float2*>(Ag + (size_t)(qr0 + 8) * S_ + col) =
                    make_float2(pn[nt][2], pn[nt][3]);
            }
        }

        sp2 = s;                    // stage s becomes the prefetch target at kt+1
        s = (s == 2) ? 0 : s + 1;
    }

    // ---- Rowsum reduce across the 4 lanes sharing each row; store 1/rowsum ----
    rs0 += __shfl_xor_sync(0xffffffffu, rs0, 1);
    rs0 += __shfl_xor_sync(0xffffffffu, rs0, 2);
    rs1 += __shfl_xor_sync(0xffffffffu, rs1, 1);
    rs1 += __shfl_xor_sync(0xffffffffu, rs1, 2);
    if ((lane & 3) == 0) {
        srs[wid * 16 + (lane >> 2)]     = 1.f / rs0;
        srs[wid * 16 + (lane >> 2) + 8] = 1.f / rs1;
    }
    __syncthreads();   // also makes all Ag writes CTA-visible

    // ---- Write output: o / rowsum ----
    {
        const float inv0 = srs[qr0];
        const float inv1 = srs[qr0 + 8];
#pragma unroll
        for (int dn = 0; dn < 8; dn++) {
            int col = dn * 8 + ((lane & 3) << 1);
            *reinterpret_cast<float2*>(Og + (size_t)qr0 * D_ + col) =
                make_float2(o[dn][0] * inv0, o[dn][1] * inv0);
            *reinterpret_cast<float2*>(Og + (size_t)(qr0 + 8) * D_ + col) =
                make_float2(o[dn][2] * inv1, o[dn][3] * inv1);
        }
    }

    // ---- Normalize sweep: attn tile (1MB) read, scale, streamed back ----
    {
        float4* A4 = reinterpret_cast<float4*>(Ag);
        constexpr int TOTAL_F4 = TQ_ * (S_ / 4);   // 65536
#pragma unroll 4
        for (int j = tid; j < TOTAL_F4; j += THREADS_) {
            int row = j >> 9;
            float inv = srs[row];
            float4 x = A4[j];
            x.x *= inv; x.y *= inv; x.z *= inv; x.w *= inv;
            __stwt(&A4[j], x);
        }
    }
}

} // namespace

extern "C" void kernel_launch(void* const* d_in, const int* in_sizes, int n_in,
                              void* d_out, int out_size) {
    (void)in_sizes; (void)n_in; (void)out_size;
    const float* q = (const float*)d_in[0];
    const float* k = (const float*)d_in[1];
    const float* v = (const float*)d_in[2];
    const int*   m = (const int*)d_in[3];
    float* out = (float*)d_out;

    convert_kernel<<<2048, 256>>>(q, k, v, m);

    cudaFuncSetAttribute(attn_kernel, cudaFuncAttributeMaxDynamicSharedMemorySize, SMEM_BYTES);
    dim3 grid(S_ / TQ_, BH_);   // x = q-tile fast-varying -> L2 K/V reuse within bh
    attn_kernel<<<grid, THREADS_, SMEM_BYTES>>>(out);
}

// round 8
// speedup vs baseline: 1.4073x; 1.0991x over previous
#include <cuda_runtime.h>
#include <cuda_bf16.h>
#include <cuda_fp16.h>
#include <cstdint>

// ============================================================================
// Fused SDPA with attn-matrix output.
// R8: PV uses p(fp16 2-split) x V(single fp16): 2 mma per step (-17% mma),
//     half the V LDSM traffic. Chunk-level software pipelining: QK(nc+1)
//     issued between exp(nc) and PV(nc). 3-stage cp.async, 1 sync/tile.
//   convert_kernel: Q(/8),K -> bf16 hi/lo; V -> fp16; mask -> float.
//   attn_kernel:    QK 3-split bf16 mma -> p=mask*exp (unnormalized attn,
//                   rowsum) -> PV fp16 mma; tail: out=acc/rowsum + sweep.
// ============================================================================

namespace {

constexpr int S_  = 2048;
constexpr int D_  = 64;
constexpr int BH_ = 32;          // B*H
constexpr int TQ_ = 128;         // queries per CTA
constexpr int KT_ = 64;          // keys per stage
constexpr int NKT_ = S_ / KT_;   // 32 tiles
constexpr int THREADS_ = 256;    // 8 warps
constexpr int ROWP_ = 72;        // padded 16-bit row (144B) -> conflict-free LDSM
constexpr int NELEM_ = BH_ * S_ * D_;   // 4.19M per tensor

// ---- scratch: Q/K bf16 hi/lo, V fp16, mask float ----
__device__ __nv_bfloat16 g_qh[NELEM_], g_ql[NELEM_];
__device__ __nv_bfloat16 g_kh[NELEM_], g_kl[NELEM_];
__device__ __half g_v[NELEM_];
__device__ float g_mf[2 * S_];

// ---- smem layout (bytes): 3 stages; Q overlays stages 1-2 during prologue ----
constexpr int KH_  = 0;
constexpr int KL_  = KH_ + KT_ * ROWP_ * 2;          // 9216
constexpr int VV_  = KL_ + KT_ * ROWP_ * 2;          // 18432
constexpr int MSK_ = VV_ + KT_ * ROWP_ * 2;          // 27648 (within stage)
constexpr int STG_SZ = MSK_ + KT_ * 4;               // 27904
constexpr int SQH_OFF = STG_SZ;                      // Q hi at stage-1 base
constexpr int SQL_OFF = SQH_OFF + TQ_ * ROWP_ * 2;   // +18432 (spills into stage 2)
constexpr int SRS_OFF = 3 * STG_SZ;                  // 83712
constexpr int SMEM_BYTES = SRS_OFF + TQ_ * 4;        // 84224

__device__ __forceinline__ uint32_t smem_u32(const void* p) {
    return (uint32_t)__cvta_generic_to_shared(p);
}
__device__ __forceinline__ void cp16(uint32_t dst, const void* src) {
    asm volatile("cp.async.cg.shared.global [%0], [%1], 16;" :: "r"(dst), "l"(src));
}
#define CP_COMMIT() asm volatile("cp.async.commit_group;" ::: "memory")
#define CP_WAIT(n)  asm volatile("cp.async.wait_group %0;" :: "n"(n) : "memory")

__device__ __forceinline__ void ldsm_x4(uint32_t a[4], uint32_t addr) {
    asm volatile("ldmatrix.sync.aligned.m8n8.x4.shared.b16 {%0,%1,%2,%3}, [%4];"
                 : "=r"(a[0]), "=r"(a[1]), "=r"(a[2]), "=r"(a[3]) : "r"(addr));
}
__device__ __forceinline__ void ldsm_x4t(uint32_t a[4], uint32_t addr) {
    asm volatile("ldmatrix.sync.aligned.m8n8.x4.trans.shared.b16 {%0,%1,%2,%3}, [%4];"
                 : "=r"(a[0]), "=r"(a[1]), "=r"(a[2]), "=r"(a[3]) : "r"(addr));
}
__device__ __forceinline__ void mma_bf16(float c[4], const uint32_t a[4], const uint32_t b[2]) {
    asm volatile(
        "mma.sync.aligned.m16n8k16.row.col.f32.bf16.bf16.f32 "
        "{%0,%1,%2,%3}, {%4,%5,%6,%7}, {%8,%9}, {%0,%1,%2,%3};"
        : "+f"(c[0]), "+f"(c[1]), "+f"(c[2]), "+f"(c[3])
        : "r"(a[0]), "r"(a[1]), "r"(a[2]), "r"(a[3]), "r"(b[0]), "r"(b[1]));
}
__device__ __forceinline__ void mma_f16(float c[4], const uint32_t a[4], const uint32_t b[2]) {
    asm volatile(
        "mma.sync.aligned.m16n8k16.row.col.f32.f16.f16.f32 "
        "{%0,%1,%2,%3}, {%4,%5,%6,%7}, {%8,%9}, {%0,%1,%2,%3};"
        : "+f"(c[0]), "+f"(c[1]), "+f"(c[2]), "+f"(c[3])
        : "r"(a[0]), "r"(a[1]), "r"(a[2]), "r"(a[3]), "r"(b[0]), "r"(b[1]));
}
__device__ __forceinline__ uint32_t pack_bf16(__nv_bfloat16 lo, __nv_bfloat16 hi) {
    return ((uint32_t)__bfloat16_as_ushort(hi) << 16) | (uint32_t)__bfloat16_as_ushort(lo);
}
__device__ __forceinline__ void split2(float x, float y, uint32_t& hi, uint32_t& lo) {
    __nv_bfloat16 hx = __float2bfloat16(x);
    __nv_bfloat16 hy = __float2bfloat16(y);
    hi = pack_bf16(hx, hy);
    lo = pack_bf16(__float2bfloat16(x - __bfloat162float(hx)),
                   __float2bfloat16(y - __bfloat162float(hy)));
}
__device__ __forceinline__ void split4_u2(float4 v, uint2& h, uint2& l) {
    uint32_t h0, l0, h1, l1;
    split2(v.x, v.y, h0, l0);
    split2(v.z, v.w, h1, l1);
    h = make_uint2(h0, h1);
    l = make_uint2(l0, l1);
}
// fp16 2-split of a pair: hi = h2(x,y), lo = h2 residual.
__device__ __forceinline__ void splitf16(float x, float y, uint32_t& hi, uint32_t& lo) {
    __half2 h = __floats2half2_rn(x, y);
    hi = *reinterpret_cast<uint32_t*>(&h);
    float2 f = __half22float2(h);
    __half2 l = __floats2half2_rn(x - f.x, y - f.y);
    lo = *reinterpret_cast<uint32_t*>(&l);
}

// ---------------------------------------------------------------------------
__global__ void __launch_bounds__(256)
convert_kernel(const float* __restrict__ q, const float* __restrict__ k,
               const float* __restrict__ v, const int* __restrict__ m) {
    const int N4 = NELEM_ / 4;
    const int stride = gridDim.x * blockDim.x;
    for (int j = blockIdx.x * blockDim.x + threadIdx.x; j < N4; j += stride) {
        float4 x = reinterpret_cast<const float4*>(q)[j];
        x.x *= 0.125f; x.y *= 0.125f; x.z *= 0.125f; x.w *= 0.125f;
        uint2 h, l;
        split4_u2(x, h, l);
        reinterpret_cast<uint2*>(g_qh)[j] = h;
        reinterpret_cast<uint2*>(g_ql)[j] = l;
        split4_u2(reinterpret_cast<const float4*>(k)[j], h, l);
        reinterpret_cast<uint2*>(g_kh)[j] = h;
        reinterpret_cast<uint2*>(g_kl)[j] = l;
        float4 vv = reinterpret_cast<const float4*>(v)[j];
        __half2 v0 = __floats2half2_rn(vv.x, vv.y);
        __half2 v1 = __floats2half2_rn(vv.z, vv.w);
        reinterpret_cast<uint2*>(g_v)[j] =
            make_uint2(*reinterpret_cast<uint32_t*>(&v0), *reinterpret_cast<uint32_t*>(&v1));
    }
    for (int j = blockIdx.x * blockDim.x + threadIdx.x; j < 2 * S_; j += stride)
        g_mf[j] = m[j] ? 1.f : 0.f;
}

// Issue one K/V stage (K hi/lo bf16 + V fp16 + mask) via cp.async.
__device__ __forceinline__ void cp_tile_kv(uint32_t stg, size_t kvoff,
                                           size_t moff, int tid) {
#pragma unroll
    for (int i = 0; i < 2; i++) {
        int c = tid + THREADS_ * i;                 // 0..511
        int row = c >> 3, j = c & 7;
        uint32_t so = row * 144 + j * 16;
        size_t go = kvoff + row * 64 + j * 8;
        cp16(stg + KH_ + so, g_kh + go);
        cp16(stg + KL_ + so, g_kl + go);
        cp16(stg + VV_ + so, g_v + go);
    }
    if (tid < 16) cp16(stg + MSK_ + tid * 16, g_mf + moff + tid * 4);
}

// ---------------------------------------------------------------------------
__global__ void __launch_bounds__(THREADS_, 2)
attn_kernel(float* __restrict__ Out) {
    extern __shared__ char smem[];
    const uint32_t sb = smem_u32(smem);
    float* srs = (float*)(smem + SRS_OFF);

    const int qt = blockIdx.x;
    const int bh = blockIdx.y;
    const int tid = threadIdx.x;
    const int wid = tid >> 5;
    const int lane = tid & 31;
    const int b = bh >> 4;  // H = 16

    const size_t base = (size_t)bh * S_ * D_;
    const size_t qoff = base + (size_t)qt * TQ_ * D_;
    const size_t moff = (size_t)b * S_;
    float* Og = Out + qoff;
    float* Ag = Out + (size_t)BH_ * S_ * D_ + (size_t)bh * S_ * S_ + (size_t)qt * TQ_ * S_;

    const uint32_t stg[3] = {sb, sb + STG_SZ, sb + 2 * STG_SZ};

    // ---- Prologue: cp Q (overlaying stages 1-2), tile 0 into stage 0 ----
    {
#pragma unroll
        for (int i = 0; i < 4; i++) {
            int c = tid + THREADS_ * i;             // 0..1023
            int row = c >> 3, j = c & 7;
            uint32_t so = row * 144 + j * 16;
            size_t go = qoff + row * 64 + j * 8;
            cp16(sb + SQH_OFF + so, g_qh + go);
            cp16(sb + SQL_OFF + so, g_ql + go);
        }
        CP_COMMIT();                                // group: Q
        cp_tile_kv(stg[0], base, moff, tid);
        CP_COMMIT();                                // group: tile 0
    }
    CP_WAIT(1);                                     // Q arrived
    __syncthreads();

    // ---- Persistent Q fragments (warp's 16 queries, full D=64) ----
    uint32_t aH[4][4], aL[4][4];
    {
        int r = wid * 16 + (lane & 15);
        int ch = (lane >> 4) * 8;
        const __nv_bfloat16* sQh = (const __nv_bfloat16*)(smem + SQH_OFF);
        const __nv_bfloat16* sQl = (const __nv_bfloat16*)(smem + SQL_OFF);
#pragma unroll
        for (int ds = 0; ds < 4; ds++) {
            ldsm_x4(aH[ds], smem_u32(&sQh[r * ROWP_ + ds * 16 + ch]));
            ldsm_x4(aL[ds], smem_u32(&sQl[r * ROWP_ + ds * 16 + ch]));
        }
    }
    __syncthreads();    // all warps done reading Q -> stages 1,2 free
    cp_tile_kv(stg[1], base + KT_ * D_, moff + KT_, tid);
    CP_COMMIT();                                    // group: tile 1

    // x4 LDSM base offsets (within a stage).
    const uint32_t koff = (((lane & 7) + ((lane >> 4) << 3)) * ROWP_) * 2 + ((lane >> 3) & 1) * 16;
    const uint32_t voff = (lane & 15) * ROWP_ * 2 + (lane >> 4) * 16;
    const int rsb = ROWP_ * 2;
    const int qr0 = wid * 16 + (lane >> 2);

    float rs0 = 0.f, rs1 = 0.f;
    float o[8][4];
#pragma unroll
    for (int dn = 0; dn < 8; dn++)
#pragma unroll
        for (int c = 0; c < 4; c++) o[dn][c] = 0.f;

    // ======================= Main loop (pipelined chunks) =======================
    int s = 0;          // stage holding tile kt
    int sp2 = 2;        // prefetch target for tile kt+2
#pragma unroll 1
    for (int kt = 0; kt < NKT_; kt++) {
        CP_WAIT(1);          // tile kt arrived (kt+1 may still fly)
        __syncthreads();     // visibility + stage sp2 retired

        if (kt + 2 < NKT_)
            cp_tile_kv(stg[sp2], base + (size_t)(kt + 2) * KT_ * D_,
                       moff + (kt + 2) * KT_, tid);
        CP_COMMIT();

        const uint32_t bkh = stg[s] + KH_ + koff;
        const uint32_t bkl = stg[s] + KL_ + koff;
        const uint32_t bvv = stg[s] + VV_ + voff;
        const float* msk = (const float*)(smem + (s * STG_SZ + MSK_));

        // -- QK for chunk 0 (prologue of chunk pipeline) --
        float c0[4] = {0.f, 0.f, 0.f, 0.f}, c1[4] = {0.f, 0.f, 0.f, 0.f};
        float e0[4] = {0.f, 0.f, 0.f, 0.f}, e1[4] = {0.f, 0.f, 0.f, 0.f};
#pragma unroll
        for (int ds = 0; ds < 4; ds++) {
            uint32_t bh4[4], bl4[4];
            ldsm_x4(bh4, bkh + ds * 32);
            ldsm_x4(bl4, bkl + ds * 32);
            mma_bf16(c0, aH[ds], bh4);
            mma_bf16(c1, aH[ds], bh4 + 2);
            mma_bf16(e0, aH[ds], bl4);
            mma_bf16(e1, aH[ds], bl4 + 2);
            mma_bf16(e0, aL[ds], bh4);
            mma_bf16(e1, aL[ds], bh4 + 2);
        }

#pragma unroll
        for (int nc = 0; nc < 4; nc++) {            // 16-key chunks
            const int n0 = nc * 16;
            // -- exp for chunk nc (consumes c/e) --
            float pn[2][4];
            {
                int kc = n0 + ((lane & 3) << 1);
                float m00 = msk[kc],     m01 = msk[kc + 1];
                float m10 = msk[kc + 8], m11 = msk[kc + 9];
                pn[0][0] = m00 * __expf(c0[0] + e0[0]);
                pn[0][1] = m01 * __expf(c0[1] + e0[1]);
                pn[0][2] = m00 * __expf(c0[2] + e0[2]);
                pn[0][3] = m01 * __expf(c0[3] + e0[3]);
                pn[1][0] = m10 * __expf(c1[0] + e1[0]);
                pn[1][1] = m11 * __expf(c1[1] + e1[1]);
                pn[1][2] = m10 * __expf(c1[2] + e1[2]);
                pn[1][3] = m11 * __expf(c1[3] + e1[3]);
            }

            // -- issue QK for chunk nc+1 (independent work covering exp latency) --
            if (nc < 3) {
#pragma unroll
                for (int i = 0; i < 4; i++) { c0[i] = 0.f; c1[i] = 0.f; e0[i] = 0.f; e1[i] = 0.f; }
#pragma unroll
                for (int ds = 0; ds < 4; ds++) {
                    uint32_t bh4[4], bl4[4];
                    ldsm_x4(bh4, bkh + (n0 + 16) * rsb + ds * 32);
                    ldsm_x4(bl4, bkl + (n0 + 16) * rsb + ds * 32);
                    mma_bf16(c0, aH[ds], bh4);
                    mma_bf16(c1, aH[ds], bh4 + 2);
                    mma_bf16(e0, aH[ds], bl4);
                    mma_bf16(e1, aH[ds], bl4 + 2);
                    mma_bf16(e0, aL[ds], bh4);
                    mma_bf16(e1, aL[ds], bh4 + 2);
                }
            }

            // -- rowsum + fp16 2-split pack of p --
            rs0 += pn[0][0] + pn[0][1] + pn[1][0] + pn[1][1];
            rs1 += pn[0][2] + pn[0][3] + pn[1][2] + pn[1][3];
            uint32_t ph[4], pl[4];
            splitf16(pn[0][0], pn[0][1], ph[0], pl[0]);
            splitf16(pn[0][2], pn[0][3], ph[1], pl[1]);
            splitf16(pn[1][0], pn[1][1], ph[2], pl[2]);
            splitf16(pn[1][2], pn[1][3], ph[3], pl[3]);

            // -- PV for chunk nc: 2 fp16 mma per n8-tile --
#pragma unroll
            for (int dp = 0; dp < 4; dp++) {        // d-column pairs
                uint32_t v4[4];
                ldsm_x4t(v4, bvv + n0 * rsb + dp * 32);
                mma_f16(o[2 * dp],     ph, v4);
                mma_f16(o[2 * dp],     pl, v4);
                mma_f16(o[2 * dp + 1], ph, v4 + 2);
                mma_f16(o[2 * dp + 1], pl, v4 + 2);
            }

            // -- write UNNORMALIZED p --
#pragma unroll
            for (int nt = 0; nt < 2; nt++) {
                int col = kt * KT_ + n0 + nt * 8 + ((lane & 3) << 1);
                *reinterpret_cast<float2*>(Ag + (size_t)qr0 * S_ + col) =
                    make_float2(pn[nt][0], pn[nt][1]);
                *reinterpret_cast<float2*>(Ag + (size_t)(qr0 + 8) * S_ + col) =
                    make_float2(pn[nt][2], pn[nt][3]);
            }
        }

        sp2 = s;
        s = (s == 2) ? 0 : s + 1;
    }

    // ---- Rowsum reduce across the 4 lanes sharing each row; store 1/rowsum ----
    rs0 += __shfl_xor_sync(0xffffffffu, rs0, 1);
    rs0 += __shfl_xor_sync(0xffffffffu, rs0, 2);
    rs1 += __shfl_xor_sync(0xffffffffu, rs1, 1);
    rs1 += __shfl_xor_sync(0xffffffffu, rs1, 2);
    if ((lane & 3) == 0) {
        srs[wid * 16 + (lane >> 2)]     = 1.f / rs0;
        srs[wid * 16 + (lane >> 2) + 8] = 1.f / rs1;
    }
    __syncthreads();   // also makes all Ag writes CTA-visible

    // ---- Write output: o / rowsum ----
    {
        const float inv0 = srs[qr0];
        const float inv1 = srs[qr0 + 8];
#pragma unroll
        for (int dn = 0; dn < 8; dn++) {
            int col = dn * 8 + ((lane & 3) << 1);
            *reinterpret_cast<float2*>(Og + (size_t)qr0 * D_ + col) =
                make_float2(o[dn][0] * inv0, o[dn][1] * inv0);
            *reinterpret_cast<float2*>(Og + (size_t)(qr0 + 8) * D_ + col) =
                make_float2(o[dn][2] * inv1, o[dn][3] * inv1);
        }
    }

    // ---- Normalize sweep: attn tile (1MB) read, scale, streamed back ----
    {
        float4* A4 = reinterpret_cast<float4*>(Ag);
        constexpr int TOTAL_F4 = TQ_ * (S_ / 4);   // 65536
#pragma unroll 4
        for (int j = tid; j < TOTAL_F4; j += THREADS_) {
            int row = j >> 9;
            float inv = srs[row];
            float4 x = A4[j];
            x.x *= inv; x.y *= inv; x.z *= inv; x.w *= inv;
            __stwt(&A4[j], x);
        }
    }
}

} // namespace

extern "C" void kernel_launch(void* const* d_in, const int* in_sizes, int n_in,
                              void* d_out, int out_size) {
    (void)in_sizes; (void)n_in; (void)out_size;
    const float* q = (const float*)d_in[0];
    const float* k = (const float*)d_in[1];
    const float* v = (const float*)d_in[2];
    const int*   m = (const int*)d_in[3];
    float* out = (float*)d_out;

    convert_kernel<<<2048, 256>>>(q, k, v, m);

    cudaFuncSetAttribute(attn_kernel, cudaFuncAttributeMaxDynamicSharedMemorySize, SMEM_BYTES);
    dim3 grid(S_ / TQ_, BH_);   // x = q-tile fast-varying -> L2 K/V reuse within bh
    attn_kernel<<<grid, THREADS_, SMEM_BYTES>>>(out);
}

// round 10
// speedup vs baseline: 1.7702x; 1.2579x over previous
#include <cuda_runtime.h>
#include <cuda_bf16.h>
#include <cuda_fp16.h>
#include <cstdint>

// ============================================================================
// Fused SDPA with attn-matrix output.
// R10: R9 with the rowsum_kernel Q-load bound fixed (1024 chunks, not 512).
//   convert_kernel: Q(/8),K -> bf16 hi/lo + fp16; V -> fp16; mask -> float.
//   rowsum_kernel:  cheap 1-term fp16 QK -> exp -> rowsum; writes 1/rowsum.
//   attn_kernel:    QK 3-split bf16 -> p=mask*exp*inv (NORMALIZED, __stwt to
//                   attn) -> PV fp16 (p 2-split x V fp16) -> out written as-is.
// ============================================================================

namespace {

constexpr int S_  = 2048;
constexpr int D_  = 64;
constexpr int BH_ = 32;          // B*H
constexpr int TQ_ = 128;         // queries per CTA
constexpr int KT_ = 64;          // keys per stage
constexpr int NKT_ = S_ / KT_;   // 32 tiles
constexpr int THREADS_ = 256;    // 8 warps
constexpr int ROWP_ = 72;        // padded 16-bit row (144B) -> conflict-free LDSM
constexpr int NELEM_ = BH_ * S_ * D_;   // 4.19M per tensor

// ---- scratch ----
__device__ __nv_bfloat16 g_qh[NELEM_], g_ql[NELEM_];
__device__ __nv_bfloat16 g_kh[NELEM_], g_kl[NELEM_];
__device__ __half g_qf[NELEM_], g_kf[NELEM_];
__device__ __half g_v[NELEM_];
__device__ float g_mf[2 * S_];
__device__ float g_inv[BH_ * S_];      // 1/rowsum per (bh, row)

// ---- attn kernel smem (3 stages; Q overlays stages 1-2 in prologue) ----
constexpr int KH_  = 0;
constexpr int KL_  = KH_ + KT_ * ROWP_ * 2;          // 9216
constexpr int VV_  = KL_ + KT_ * ROWP_ * 2;          // 18432
constexpr int MSK_ = VV_ + KT_ * ROWP_ * 2;          // 27648 (within stage)
constexpr int STG_SZ = MSK_ + KT_ * 4;               // 27904
constexpr int SQH_OFF = STG_SZ;                      // Q hi at stage-1 base
constexpr int SQL_OFF = SQH_OFF + TQ_ * ROWP_ * 2;   // +18432 (into stage 2)
constexpr int SMEM_BYTES = 3 * STG_SZ;               // 83712

// ---- rowsum kernel smem (separate Q region + 3 small stages) ----
constexpr int RQ_OFF = 0;                            // Q fp16: 18432
constexpr int RSTG_OFF = TQ_ * ROWP_ * 2;            // 18432
constexpr int RKF_ = 0;
constexpr int RMSK_ = KT_ * ROWP_ * 2;               // 9216 (within stage)
constexpr int RSTG_SZ = RMSK_ + KT_ * 4;             // 9472
constexpr int RSMEM_BYTES = RSTG_OFF + 3 * RSTG_SZ;  // 46848

__device__ __forceinline__ uint32_t smem_u32(const void* p) {
    return (uint32_t)__cvta_generic_to_shared(p);
}
__device__ __forceinline__ void cp16(uint32_t dst, const void* src) {
    asm volatile("cp.async.cg.shared.global [%0], [%1], 16;" :: "r"(dst), "l"(src));
}
#define CP_COMMIT() asm volatile("cp.async.commit_group;" ::: "memory")
#define CP_WAIT(n)  asm volatile("cp.async.wait_group %0;" :: "n"(n) : "memory")

__device__ __forceinline__ void ldsm_x4(uint32_t a[4], uint32_t addr) {
    asm volatile("ldmatrix.sync.aligned.m8n8.x4.shared.b16 {%0,%1,%2,%3}, [%4];"
                 : "=r"(a[0]), "=r"(a[1]), "=r"(a[2]), "=r"(a[3]) : "r"(addr));
}
__device__ __forceinline__ void ldsm_x4t(uint32_t a[4], uint32_t addr) {
    asm volatile("ldmatrix.sync.aligned.m8n8.x4.trans.shared.b16 {%0,%1,%2,%3}, [%4];"
                 : "=r"(a[0]), "=r"(a[1]), "=r"(a[2]), "=r"(a[3]) : "r"(addr));
}
__device__ __forceinline__ void mma_bf16(float c[4], const uint32_t a[4], const uint32_t b[2]) {
    asm volatile(
        "mma.sync.aligned.m16n8k16.row.col.f32.bf16.bf16.f32 "
        "{%0,%1,%2,%3}, {%4,%5,%6,%7}, {%8,%9}, {%0,%1,%2,%3};"
        : "+f"(c[0]), "+f"(c[1]), "+f"(c[2]), "+f"(c[3])
        : "r"(a[0]), "r"(a[1]), "r"(a[2]), "r"(a[3]), "r"(b[0]), "r"(b[1]));
}
__device__ __forceinline__ void mma_f16(float c[4], const uint32_t a[4], const uint32_t b[2]) {
    asm volatile(
        "mma.sync.aligned.m16n8k16.row.col.f32.f16.f16.f32 "
        "{%0,%1,%2,%3}, {%4,%5,%6,%7}, {%8,%9}, {%0,%1,%2,%3};"
        : "+f"(c[0]), "+f"(c[1]), "+f"(c[2]), "+f"(c[3])
        : "r"(a[0]), "r"(a[1]), "r"(a[2]), "r"(a[3]), "r"(b[0]), "r"(b[1]));
}
__device__ __forceinline__ uint32_t pack_bf16(__nv_bfloat16 lo, __nv_bfloat16 hi) {
    return ((uint32_t)__bfloat16_as_ushort(hi) << 16) | (uint32_t)__bfloat16_as_ushort(lo);
}
__device__ __forceinline__ void split2(float x, float y, uint32_t& hi, uint32_t& lo) {
    __nv_bfloat16 hx = __float2bfloat16(x);
    __nv_bfloat16 hy = __float2bfloat16(y);
    hi = pack_bf16(hx, hy);
    lo = pack_bf16(__float2bfloat16(x - __bfloat162float(hx)),
                   __float2bfloat16(y - __bfloat162float(hy)));
}
__device__ __forceinline__ void split4_u2(float4 v, uint2& h, uint2& l) {
    uint32_t h0, l0, h1, l1;
    split2(v.x, v.y, h0, l0);
    split2(v.z, v.w, h1, l1);
    h = make_uint2(h0, h1);
    l = make_uint2(l0, l1);
}
__device__ __forceinline__ uint2 pack_f16x4(float4 v) {
    __half2 a = __floats2half2_rn(v.x, v.y);
    __half2 b = __floats2half2_rn(v.z, v.w);
    return make_uint2(*reinterpret_cast<uint32_t*>(&a), *reinterpret_cast<uint32_t*>(&b));
}
__device__ __forceinline__ void splitf16(float x, float y, uint32_t& hi, uint32_t& lo) {
    __half2 h = __floats2half2_rn(x, y);
    hi = *reinterpret_cast<uint32_t*>(&h);
    float2 f = __half22float2(h);
    __half2 l = __floats2half2_rn(x - f.x, y - f.y);
    lo = *reinterpret_cast<uint32_t*>(&l);
}

// ---------------------------------------------------------------------------
__global__ void __launch_bounds__(256)
convert_kernel(const float* __restrict__ q, const float* __restrict__ k,
               const float* __restrict__ v, const int* __restrict__ m) {
    const int N4 = NELEM_ / 4;
    const int stride = gridDim.x * blockDim.x;
    for (int j = blockIdx.x * blockDim.x + threadIdx.x; j < N4; j += stride) {
        float4 x = reinterpret_cast<const float4*>(q)[j];
        x.x *= 0.125f; x.y *= 0.125f; x.z *= 0.125f; x.w *= 0.125f;
        uint2 h, l;
        split4_u2(x, h, l);
        reinterpret_cast<uint2*>(g_qh)[j] = h;
        reinterpret_cast<uint2*>(g_ql)[j] = l;
        reinterpret_cast<uint2*>(g_qf)[j] = pack_f16x4(x);
        float4 kk = reinterpret_cast<const float4*>(k)[j];
        split4_u2(kk, h, l);
        reinterpret_cast<uint2*>(g_kh)[j] = h;
        reinterpret_cast<uint2*>(g_kl)[j] = l;
        reinterpret_cast<uint2*>(g_kf)[j] = pack_f16x4(kk);
        reinterpret_cast<uint2*>(g_v)[j] = pack_f16x4(reinterpret_cast<const float4*>(v)[j]);
    }
    for (int j = blockIdx.x * blockDim.x + threadIdx.x; j < 2 * S_; j += stride)
        g_mf[j] = m[j] ? 1.f : 0.f;
}

// ---------------------------------------------------------------------------
// rowsum_kernel: 1-term fp16 QK -> exp -> rowsum; writes g_inv = 1/rowsum.
// ---------------------------------------------------------------------------
__device__ __forceinline__ void cp_tile_k16(uint32_t stg, size_t kvoff,
                                            size_t moff, int tid) {
#pragma unroll
    for (int i = 0; i < 2; i++) {
        int c = tid + THREADS_ * i;                 // 0..511 (64 rows x 8 chunks)
        int row = c >> 3, j = c & 7;
        cp16(stg + RKF_ + row * 144 + j * 16, g_kf + kvoff + row * 64 + j * 8);
    }
    if (tid < 16) cp16(stg + RMSK_ + tid * 16, g_mf + moff + tid * 4);
}

__global__ void __launch_bounds__(THREADS_, 3)
rowsum_kernel() {
    extern __shared__ char smem[];
    const uint32_t sb = smem_u32(smem);

    const int qt = blockIdx.x;
    const int bh = blockIdx.y;
    const int tid = threadIdx.x;
    const int wid = tid >> 5;
    const int lane = tid & 31;
    const int b = bh >> 4;

    const size_t base = (size_t)bh * S_ * D_;
    const size_t qoff = base + (size_t)qt * TQ_ * D_;
    const size_t moff = (size_t)b * S_;

    const uint32_t stg[3] = {sb + RSTG_OFF, sb + RSTG_OFF + RSTG_SZ,
                             sb + RSTG_OFF + 2 * RSTG_SZ};

    // Prologue: Q fp16 (128 rows x 8 chunks = 1024 chunks!) + tiles 0,1
    {
#pragma unroll
        for (int i = 0; i < 4; i++) {
            int c = tid + THREADS_ * i;             // 0..1023
            int row = c >> 3, j = c & 7;
            cp16(sb + RQ_OFF + row * 144 + j * 16, g_qf + qoff + row * 64 + j * 8);
        }
        cp_tile_k16(stg[0], base, moff, tid);
        CP_COMMIT();
        cp_tile_k16(stg[1], base + KT_ * D_, moff + KT_, tid);
        CP_COMMIT();
    }
    CP_WAIT(1);
    __syncthreads();

    // Q fragments
    uint32_t qf[4][4];
    {
        int r = wid * 16 + (lane & 15);
        int ch = (lane >> 4) * 8;
        const __half* sQ = (const __half*)(smem + RQ_OFF);
#pragma unroll
        for (int ds = 0; ds < 4; ds++)
            ldsm_x4(qf[ds], smem_u32(&sQ[r * ROWP_ + ds * 16 + ch]));
    }

    const uint32_t koff = (((lane & 7) + ((lane >> 4) << 3)) * ROWP_) * 2 + ((lane >> 3) & 1) * 16;
    const int rsb = ROWP_ * 2;
    float rs0 = 0.f, rs1 = 0.f;

    int s = 0, sp2 = 2;
#pragma unroll 1
    for (int kt = 0; kt < NKT_; kt++) {
        if (kt > 0) { CP_WAIT(1); __syncthreads(); }
        if (kt + 2 < NKT_)
            cp_tile_k16(stg[sp2], base + (size_t)(kt + 2) * KT_ * D_,
                        moff + (kt + 2) * KT_, tid);
        CP_COMMIT();

        const uint32_t bkf = stg[s] + RKF_ + koff;
        const float* msk = (const float*)(smem + RSTG_OFF + s * RSTG_SZ + RMSK_);

#pragma unroll
        for (int nc = 0; nc < 4; nc++) {
            const int n0 = nc * 16;
            float c0[4] = {0.f, 0.f, 0.f, 0.f};
            float c1[4] = {0.f, 0.f, 0.f, 0.f};
#pragma unroll
            for (int ds = 0; ds < 4; ds++) {
                uint32_t k4[4];
                ldsm_x4(k4, bkf + n0 * rsb + ds * 32);
                mma_f16(c0, qf[ds], k4);
                mma_f16(c1, qf[ds], k4 + 2);
            }
            int kc = n0 + ((lane & 3) << 1);
            float m00 = msk[kc],     m01 = msk[kc + 1];
            float m10 = msk[kc + 8], m11 = msk[kc + 9];
            rs0 += m00 * __expf(c0[0]) + m01 * __expf(c0[1])
                 + m10 * __expf(c1[0]) + m11 * __expf(c1[1]);
            rs1 += m00 * __expf(c0[2]) + m01 * __expf(c0[3])
                 + m10 * __expf(c1[2]) + m11 * __expf(c1[3]);
        }
        sp2 = s;
        s = (s == 2) ? 0 : s + 1;
    }

    rs0 += __shfl_xor_sync(0xffffffffu, rs0, 1);
    rs0 += __shfl_xor_sync(0xffffffffu, rs0, 2);
    rs1 += __shfl_xor_sync(0xffffffffu, rs1, 1);
    rs1 += __shfl_xor_sync(0xffffffffu, rs1, 2);
    if ((lane & 3) == 0) {
        int r = qt * TQ_ + wid * 16 + (lane >> 2);
        g_inv[bh * S_ + r]     = 1.f / rs0;
        g_inv[bh * S_ + r + 8] = 1.f / rs1;
    }
}

// ---------------------------------------------------------------------------
// Main attention kernel: writes NORMALIZED attn directly (no sweep).
// ---------------------------------------------------------------------------
__device__ __forceinline__ void cp_tile_kv(uint32_t stg, size_t kvoff,
                                           size_t moff, int tid) {
#pragma unroll
    for (int i = 0; i < 2; i++) {
        int c = tid + THREADS_ * i;                 // 0..511
        int row = c >> 3, j = c & 7;
        uint32_t so = row * 144 + j * 16;
        size_t go = kvoff + row * 64 + j * 8;
        cp16(stg + KH_ + so, g_kh + go);
        cp16(stg + KL_ + so, g_kl + go);
        cp16(stg + VV_ + so, g_v + go);
    }
    if (tid < 16) cp16(stg + MSK_ + tid * 16, g_mf + moff + tid * 4);
}

__global__ void __launch_bounds__(THREADS_, 2)
attn_kernel(float* __restrict__ Out) {
    extern __shared__ char smem[];
    const uint32_t sb = smem_u32(smem);

    const int qt = blockIdx.x;
    const int bh = blockIdx.y;
    const int tid = threadIdx.x;
    const int wid = tid >> 5;
    const int lane = tid & 31;
    const int b = bh >> 4;

    const size_t base = (size_t)bh * S_ * D_;
    const size_t qoff = base + (size_t)qt * TQ_ * D_;
    const size_t moff = (size_t)b * S_;
    float* Og = Out + qoff;
    float* Ag = Out + (size_t)BH_ * S_ * D_ + (size_t)bh * S_ * S_ + (size_t)qt * TQ_ * S_;

    const uint32_t stg[3] = {sb, sb + STG_SZ, sb + 2 * STG_SZ};

    // Prologue: Q (overlaying stages 1-2), tile 0
    {
#pragma unroll
        for (int i = 0; i < 4; i++) {
            int c = tid + THREADS_ * i;             // 0..1023
            int row = c >> 3, j = c & 7;
            uint32_t so = row * 144 + j * 16;
            size_t go = qoff + row * 64 + j * 8;
            cp16(sb + SQH_OFF + so, g_qh + go);
            cp16(sb + SQL_OFF + so, g_ql + go);
        }
        CP_COMMIT();                                // group: Q
        cp_tile_kv(stg[0], base, moff, tid);
        CP_COMMIT();                                // group: tile 0
    }
    CP_WAIT(1);                                     // Q arrived
    __syncthreads();

    // Q fragments
    uint32_t aH[4][4], aL[4][4];
    {
        int r = wid * 16 + (lane & 15);
        int ch = (lane >> 4) * 8;
        const __nv_bfloat16* sQh = (const __nv_bfloat16*)(smem + SQH_OFF);
        const __nv_bfloat16* sQl = (const __nv_bfloat16*)(smem + SQL_OFF);
#pragma unroll
        for (int ds = 0; ds < 4; ds++) {
            ldsm_x4(aH[ds], smem_u32(&sQh[r * ROWP_ + ds * 16 + ch]));
            ldsm_x4(aL[ds], smem_u32(&sQl[r * ROWP_ + ds * 16 + ch]));
        }
    }
    __syncthreads();    // stages 1,2 free
    cp_tile_kv(stg[1], base + KT_ * D_, moff + KT_, tid);
    CP_COMMIT();                                    // group: tile 1

    const uint32_t koff = (((lane & 7) + ((lane >> 4) << 3)) * ROWP_) * 2 + ((lane >> 3) & 1) * 16;
    const uint32_t voff = (lane & 15) * ROWP_ * 2 + (lane >> 4) * 16;
    const int rsb = ROWP_ * 2;
    const int qr0 = wid * 16 + (lane >> 2);

    // Per-row inverse rowsums (from rowsum_kernel)
    const float inv0 = g_inv[bh * S_ + qt * TQ_ + qr0];
    const float inv1 = g_inv[bh * S_ + qt * TQ_ + qr0 + 8];

    float o[8][4];
#pragma unroll
    for (int dn = 0; dn < 8; dn++)
#pragma unroll
        for (int c = 0; c < 4; c++) o[dn][c] = 0.f;

    int s = 0, sp2 = 2;
#pragma unroll 1
    for (int kt = 0; kt < NKT_; kt++) {
        CP_WAIT(1);
        __syncthreads();

        if (kt + 2 < NKT_)
            cp_tile_kv(stg[sp2], base + (size_t)(kt + 2) * KT_ * D_,
                       moff + (kt + 2) * KT_, tid);
        CP_COMMIT();

        const uint32_t bkh = stg[s] + KH_ + koff;
        const uint32_t bkl = stg[s] + KL_ + koff;
        const uint32_t bvv = stg[s] + VV_ + voff;
        const float* msk = (const float*)(smem + (s * STG_SZ + MSK_));

        // QK for chunk 0
        float c0[4] = {0.f, 0.f, 0.f, 0.f}, c1[4] = {0.f, 0.f, 0.f, 0.f};
        float e0[4] = {0.f, 0.f, 0.f, 0.f}, e1[4] = {0.f, 0.f, 0.f, 0.f};
#pragma unroll
        for (int ds = 0; ds < 4; ds++) {
            uint32_t bh4[4], bl4[4];
            ldsm_x4(bh4, bkh + ds * 32);
            ldsm_x4(bl4, bkl + ds * 32);
            mma_bf16(c0, aH[ds], bh4);
            mma_bf16(c1, aH[ds], bh4 + 2);
            mma_bf16(e0, aH[ds], bl4);
            mma_bf16(e1, aH[ds], bl4 + 2);
            mma_bf16(e0, aL[ds], bh4);
            mma_bf16(e1, aL[ds], bh4 + 2);
        }

#pragma unroll
        for (int nc = 0; nc < 4; nc++) {
            const int n0 = nc * 16;
            // exp + normalize (final attn values)
            float pn[2][4];
            {
                int kc = n0 + ((lane & 3) << 1);
                float m00 = msk[kc] * inv0,     m01 = msk[kc + 1] * inv0;
                float m10 = msk[kc + 8] * inv0, m11 = msk[kc + 9] * inv0;
                float n00 = msk[kc] * inv1,     n01 = msk[kc + 1] * inv1;
                float n10 = msk[kc + 8] * inv1, n11 = msk[kc + 9] * inv1;
                pn[0][0] = m00 * __expf(c0[0] + e0[0]);
                pn[0][1] = m01 * __expf(c0[1] + e0[1]);
                pn[0][2] = n00 * __expf(c0[2] + e0[2]);
                pn[0][3] = n01 * __expf(c0[3] + e0[3]);
                pn[1][0] = m10 * __expf(c1[0] + e1[0]);
                pn[1][1] = m11 * __expf(c1[1] + e1[1]);
                pn[1][2] = n10 * __expf(c1[2] + e1[2]);
                pn[1][3] = n11 * __expf(c1[3] + e1[3]);
            }

            // QK for chunk nc+1 (covers exp latency)
            if (nc < 3) {
#pragma unroll
                for (int i = 0; i < 4; i++) { c0[i] = 0.f; c1[i] = 0.f; e0[i] = 0.f; e1[i] = 0.f; }
#pragma unroll
                for (int ds = 0; ds < 4; ds++) {
                    uint32_t bh4[4], bl4[4];
                    ldsm_x4(bh4, bkh + (n0 + 16) * rsb + ds * 32);
                    ldsm_x4(bl4, bkl + (n0 + 16) * rsb + ds * 32);
                    mma_bf16(c0, aH[ds], bh4);
                    mma_bf16(c1, aH[ds], bh4 + 2);
                    mma_bf16(e0, aH[ds], bl4);
                    mma_bf16(e1, aH[ds], bl4 + 2);
                    mma_bf16(e0, aL[ds], bh4);
                    mma_bf16(e1, aL[ds], bh4 + 2);
                }
            }

            // pack normalized p (fp16 2-split)
            uint32_t ph[4], pl[4];
            splitf16(pn[0][0], pn[0][1], ph[0], pl[0]);
            splitf16(pn[0][2], pn[0][3], ph[1], pl[1]);
            splitf16(pn[1][0], pn[1][1], ph[2], pl[2]);
            splitf16(pn[1][2], pn[1][3], ph[3], pl[3]);

            // PV
#pragma unroll
            for (int dp = 0; dp < 4; dp++) {
                uint32_t v4[4];
                ldsm_x4t(v4, bvv + n0 * rsb + dp * 32);
                mma_f16(o[2 * dp],     ph, v4);
                mma_f16(o[2 * dp],     pl, v4);
                mma_f16(o[2 * dp + 1], ph, v4 + 2);
                mma_f16(o[2 * dp + 1], pl, v4 + 2);
            }

            // Final attn store (streaming: never re-read)
#pragma unroll
            for (int nt = 0; nt < 2; nt++) {
                int col = kt * KT_ + n0 + nt * 8 + ((lane & 3) << 1);
                __stwt(reinterpret_cast<float2*>(Ag + (size_t)qr0 * S_ + col),
                       make_float2(pn[nt][0], pn[nt][1]));
                __stwt(reinterpret_cast<float2*>(Ag + (size_t)(qr0 + 8) * S_ + col),
                       make_float2(pn[nt][2], pn[nt][3]));
            }
        }

        sp2 = s;
        s = (s == 2) ? 0 : s + 1;
    }

    // out = o (p was already normalized before PV)
#pragma unroll
    for (int dn = 0; dn < 8; dn++) {
        int col = dn * 8 + ((lane & 3) << 1);
        *reinterpret_cast<float2*>(Og + (size_t)qr0 * D_ + col) =
            make_float2(o[dn][0], o[dn][1]);
        *reinterpret_cast<float2*>(Og + (size_t)(qr0 + 8) * D_ + col) =
            make_float2(o[dn][2], o[dn][3]);
    }
}

} // namespace

extern "C" void kernel_launch(void* const* d_in, const int* in_sizes, int n_in,
                              void* d_out, int out_size) {
    (void)in_sizes; (void)n_in; (void)out_size;
    const float* q = (const float*)d_in[0];
    const float* k = (const float*)d_in[1];
    const float* v = (const float*)d_in[2];
    const int*   m = (const int*)d_in[3];
    float* out = (float*)d_out;

    convert_kernel<<<2048, 256>>>(q, k, v, m);

    cudaFuncSetAttribute(rowsum_kernel, cudaFuncAttributeMaxDynamicSharedMemorySize, RSMEM_BYTES);
    dim3 grid(S_ / TQ_, BH_);
    rowsum_kernel<<<grid, THREADS_, RSMEM_BYTES>>>();

    cudaFuncSetAttribute(attn_kernel, cudaFuncAttributeMaxDynamicSharedMemorySize, SMEM_BYTES);
    attn_kernel<<<grid, THREADS_, SMEM_BYTES>>>(out);
}

// round 11
// speedup vs baseline: 2.0036x; 1.1318x over previous
#include <cuda_runtime.h>
#include <cuda_bf16.h>
#include <cuda_fp16.h>
#include <cstdint>

// ============================================================================
// Fused SDPA with attn-matrix output.
// R11: QK switched to 2-term fp16 (Q = exact fp16 hi+lo split, K = single
//      fp16). -25% mma, -33% loop LDSM, -50% K smem/cp traffic.
//   convert_kernel: Q(/8) -> fp16 hi/lo; K,V -> fp16; mask -> float.
//   rowsum_kernel:  1-term fp16 QK (q hi only) -> exp -> rowsum -> 1/rowsum.
//   attn_kernel:    QK 2-term fp16 -> p=mask*exp*inv (NORMALIZED, __stwt)
//                   -> PV fp16 (p 2-split x V fp16) -> out written as-is.
// ============================================================================

namespace {

constexpr int S_  = 2048;
constexpr int D_  = 64;
constexpr int BH_ = 32;          // B*H
constexpr int TQ_ = 128;         // queries per CTA
constexpr int KT_ = 64;          // keys per stage
constexpr int NKT_ = S_ / KT_;   // 32 tiles
constexpr int THREADS_ = 256;    // 8 warps
constexpr int ROWP_ = 72;        // padded 16-bit row (144B) -> conflict-free LDSM
constexpr int NELEM_ = BH_ * S_ * D_;   // 4.19M per tensor

// ---- scratch ----
__device__ __half g_qh[NELEM_], g_ql[NELEM_];   // Q/8, exact fp16 2-split
__device__ __half g_kf[NELEM_];                 // K fp16
__device__ __half g_v[NELEM_];                  // V fp16
__device__ float g_mf[2 * S_];
__device__ float g_inv[BH_ * S_];               // 1/rowsum per (bh, row)

// ---- attn kernel smem (3 stages; Q overlays stages 1-2 in prologue) ----
constexpr int KF_  = 0;
constexpr int VV_  = KF_ + KT_ * ROWP_ * 2;          // 9216
constexpr int MSK_ = VV_ + KT_ * ROWP_ * 2;          // 18432 (within stage)
constexpr int STG_SZ = MSK_ + KT_ * 4;               // 18688
constexpr int SQH_OFF = STG_SZ;                      // Q hi at stage-1 base
constexpr int SQL_OFF = SQH_OFF + TQ_ * ROWP_ * 2;   // +18432 (into stage 2)
constexpr int SMEM_BYTES = 3 * STG_SZ;               // 56064

// ---- rowsum kernel smem (separate Q region + 3 small stages) ----
constexpr int RQ_OFF = 0;                            // Q fp16 hi: 18432
constexpr int RSTG_OFF = TQ_ * ROWP_ * 2;            // 18432
constexpr int RKF_ = 0;
constexpr int RMSK_ = KT_ * ROWP_ * 2;               // 9216 (within stage)
constexpr int RSTG_SZ = RMSK_ + KT_ * 4;             // 9472
constexpr int RSMEM_BYTES = RSTG_OFF + 3 * RSTG_SZ;  // 46848

__device__ __forceinline__ uint32_t smem_u32(const void* p) {
    return (uint32_t)__cvta_generic_to_shared(p);
}
__device__ __forceinline__ void cp16(uint32_t dst, const void* src) {
    asm volatile("cp.async.cg.shared.global [%0], [%1], 16;" :: "r"(dst), "l"(src));
}
#define CP_COMMIT() asm volatile("cp.async.commit_group;" ::: "memory")
#define CP_WAIT(n)  asm volatile("cp.async.wait_group %0;" :: "n"(n) : "memory")

__device__ __forceinline__ void ldsm_x4(uint32_t a[4], uint32_t addr) {
    asm volatile("ldmatrix.sync.aligned.m8n8.x4.shared.b16 {%0,%1,%2,%3}, [%4];"
                 : "=r"(a[0]), "=r"(a[1]), "=r"(a[2]), "=r"(a[3]) : "r"(addr));
}
__device__ __forceinline__ void ldsm_x4t(uint32_t a[4], uint32_t addr) {
    asm volatile("ldmatrix.sync.aligned.m8n8.x4.trans.shared.b16 {%0,%1,%2,%3}, [%4];"
                 : "=r"(a[0]), "=r"(a[1]), "=r"(a[2]), "=r"(a[3]) : "r"(addr));
}
__device__ __forceinline__ void mma_f16(float c[4], const uint32_t a[4], const uint32_t b[2]) {
    asm volatile(
        "mma.sync.aligned.m16n8k16.row.col.f32.f16.f16.f32 "
        "{%0,%1,%2,%3}, {%4,%5,%6,%7}, {%8,%9}, {%0,%1,%2,%3};"
        : "+f"(c[0]), "+f"(c[1]), "+f"(c[2]), "+f"(c[3])
        : "r"(a[0]), "r"(a[1]), "r"(a[2]), "r"(a[3]), "r"(b[0]), "r"(b[1]));
}
__device__ __forceinline__ uint2 pack_f16x4(float4 v) {
    __half2 a = __floats2half2_rn(v.x, v.y);
    __half2 b = __floats2half2_rn(v.z, v.w);
    return make_uint2(*reinterpret_cast<uint32_t*>(&a), *reinterpret_cast<uint32_t*>(&b));
}
__device__ __forceinline__ void splitf16(float x, float y, uint32_t& hi, uint32_t& lo) {
    __half2 h = __floats2half2_rn(x, y);
    hi = *reinterpret_cast<uint32_t*>(&h);
    float2 f = __half22float2(h);
    __half2 l = __floats2half2_rn(x - f.x, y - f.y);
    lo = *reinterpret_cast<uint32_t*>(&l);
}

// ---------------------------------------------------------------------------
__global__ void __launch_bounds__(256)
convert_kernel(const float* __restrict__ q, const float* __restrict__ k,
               const float* __restrict__ v, const int* __restrict__ m) {
    const int N4 = NELEM_ / 4;
    const int stride = gridDim.x * blockDim.x;
    for (int j = blockIdx.x * blockDim.x + threadIdx.x; j < N4; j += stride) {
        float4 x = reinterpret_cast<const float4*>(q)[j];
        x.x *= 0.125f; x.y *= 0.125f; x.z *= 0.125f; x.w *= 0.125f;
        uint2 h, l;
        splitf16(x.x, x.y, h.x, l.x);
        splitf16(x.z, x.w, h.y, l.y);
        reinterpret_cast<uint2*>(g_qh)[j] = h;
        reinterpret_cast<uint2*>(g_ql)[j] = l;
        reinterpret_cast<uint2*>(g_kf)[j] = pack_f16x4(reinterpret_cast<const float4*>(k)[j]);
        reinterpret_cast<uint2*>(g_v)[j]  = pack_f16x4(reinterpret_cast<const float4*>(v)[j]);
    }
    for (int j = blockIdx.x * blockDim.x + threadIdx.x; j < 2 * S_; j += stride)
        g_mf[j] = m[j] ? 1.f : 0.f;
}

// ---------------------------------------------------------------------------
// rowsum_kernel: 1-term fp16 QK (q hi only) -> exp -> rowsum; writes 1/rowsum.
// ---------------------------------------------------------------------------
__device__ __forceinline__ void cp_tile_k16(uint32_t stg, size_t kvoff,
                                            size_t moff, int tid) {
#pragma unroll
    for (int i = 0; i < 2; i++) {
        int c = tid + THREADS_ * i;                 // 0..511 (64 rows x 8 chunks)
        int row = c >> 3, j = c & 7;
        cp16(stg + RKF_ + row * 144 + j * 16, g_kf + kvoff + row * 64 + j * 8);
    }
    if (tid < 16) cp16(stg + RMSK_ + tid * 16, g_mf + moff + tid * 4);
}

__global__ void __launch_bounds__(THREADS_, 3)
rowsum_kernel() {
    extern __shared__ char smem[];
    const uint32_t sb = smem_u32(smem);

    const int qt = blockIdx.x;
    const int bh = blockIdx.y;
    const int tid = threadIdx.x;
    const int wid = tid >> 5;
    const int lane = tid & 31;
    const int b = bh >> 4;

    const size_t base = (size_t)bh * S_ * D_;
    const size_t qoff = base + (size_t)qt * TQ_ * D_;
    const size_t moff = (size_t)b * S_;

    const uint32_t stg[3] = {sb + RSTG_OFF, sb + RSTG_OFF + RSTG_SZ,
                             sb + RSTG_OFF + 2 * RSTG_SZ};

    // Prologue: Q fp16 hi (128 rows x 8 chunks = 1024) + tiles 0,1
    {
#pragma unroll
        for (int i = 0; i < 4; i++) {
            int c = tid + THREADS_ * i;             // 0..1023
            int row = c >> 3, j = c & 7;
            cp16(sb + RQ_OFF + row * 144 + j * 16, g_qh + qoff + row * 64 + j * 8);
        }
        cp_tile_k16(stg[0], base, moff, tid);
        CP_COMMIT();
        cp_tile_k16(stg[1], base + KT_ * D_, moff + KT_, tid);
        CP_COMMIT();
    }
    CP_WAIT(1);
    __syncthreads();

    // Q fragments (hi only)
    uint32_t qf[4][4];
    {
        int r = wid * 16 + (lane & 15);
        int ch = (lane >> 4) * 8;
        const __half* sQ = (const __half*)(smem + RQ_OFF);
#pragma unroll
        for (int ds = 0; ds < 4; ds++)
            ldsm_x4(qf[ds], smem_u32(&sQ[r * ROWP_ + ds * 16 + ch]));
    }

    const uint32_t koff = (((lane & 7) + ((lane >> 4) << 3)) * ROWP_) * 2 + ((lane >> 3) & 1) * 16;
    const int rsb = ROWP_ * 2;
    float rs0 = 0.f, rs1 = 0.f;

    int s = 0, sp2 = 2;
#pragma unroll 1
    for (int kt = 0; kt < NKT_; kt++) {
        if (kt > 0) { CP_WAIT(1); __syncthreads(); }
        if (kt + 2 < NKT_)
            cp_tile_k16(stg[sp2], base + (size_t)(kt + 2) * KT_ * D_,
                        moff + (kt + 2) * KT_, tid);
        CP_COMMIT();

        const uint32_t bkf = stg[s] + RKF_ + koff;
        const float* msk = (const float*)(smem + RSTG_OFF + s * RSTG_SZ + RMSK_);

#pragma unroll
        for (int nc = 0; nc < 4; nc++) {
            const int n0 = nc * 16;
            float c0[4] = {0.f, 0.f, 0.f, 0.f};
            float c1[4] = {0.f, 0.f, 0.f, 0.f};
#pragma unroll
            for (int ds = 0; ds < 4; ds++) {
                uint32_t k4[4];
                ldsm_x4(k4, bkf + n0 * rsb + ds * 32);
                mma_f16(c0, qf[ds], k4);
                mma_f16(c1, qf[ds], k4 + 2);
            }
            int kc = n0 + ((lane & 3) << 1);
            float m00 = msk[kc],     m01 = msk[kc + 1];
            float m10 = msk[kc + 8], m11 = msk[kc + 9];
            rs0 += m00 * __expf(c0[0]) + m01 * __expf(c0[1])
                 + m10 * __expf(c1[0]) + m11 * __expf(c1[1]);
            rs1 += m00 * __expf(c0[2]) + m01 * __expf(c0[3])
                 + m10 * __expf(c1[2]) + m11 * __expf(c1[3]);
        }
        sp2 = s;
        s = (s == 2) ? 0 : s + 1;
    }

    rs0 += __shfl_xor_sync(0xffffffffu, rs0, 1);
    rs0 += __shfl_xor_sync(0xffffffffu, rs0, 2);
    rs1 += __shfl_xor_sync(0xffffffffu, rs1, 1);
    rs1 += __shfl_xor_sync(0xffffffffu, rs1, 2);
    if ((lane & 3) == 0) {
        int r = qt * TQ_ + wid * 16 + (lane >> 2);
        g_inv[bh * S_ + r]     = 1.f / rs0;
        g_inv[bh * S_ + r + 8] = 1.f / rs1;
    }
}

// ---------------------------------------------------------------------------
// Main attention kernel: writes NORMALIZED attn directly (no sweep).
// ---------------------------------------------------------------------------
__device__ __forceinline__ void cp_tile_kv(uint32_t stg, size_t kvoff,
                                           size_t moff, int tid) {
#pragma unroll
    for (int i = 0; i < 2; i++) {
        int c = tid + THREADS_ * i;                 // 0..511
        int row = c >> 3, j = c & 7;
        uint32_t so = row * 144 + j * 16;
        size_t go = kvoff + row * 64 + j * 8;
        cp16(stg + KF_ + so, g_kf + go);
        cp16(stg + VV_ + so, g_v + go);
    }
    if (tid < 16) cp16(stg + MSK_ + tid * 16, g_mf + moff + tid * 4);
}

__global__ void __launch_bounds__(THREADS_, 2)
attn_kernel(float* __restrict__ Out) {
    extern __shared__ char smem[];
    const uint32_t sb = smem_u32(smem);

    const int qt = blockIdx.x;
    const int bh = blockIdx.y;
    const int tid = threadIdx.x;
    const int wid = tid >> 5;
    const int lane = tid & 31;
    const int b = bh >> 4;

    const size_t base = (size_t)bh * S_ * D_;
    const size_t qoff = base + (size_t)qt * TQ_ * D_;
    const size_t moff = (size_t)b * S_;
    float* Og = Out + qoff;
    float* Ag = Out + (size_t)BH_ * S_ * D_ + (size_t)bh * S_ * S_ + (size_t)qt * TQ_ * S_;

    const uint32_t stg[3] = {sb, sb + STG_SZ, sb + 2 * STG_SZ};

    // Prologue: Q hi/lo (overlaying stages 1-2), tile 0
    {
#pragma unroll
        for (int i = 0; i < 4; i++) {
            int c = tid + THREADS_ * i;             // 0..1023
            int row = c >> 3, j = c & 7;
            uint32_t so = row * 144 + j * 16;
            size_t go = qoff + row * 64 + j * 8;
            cp16(sb + SQH_OFF + so, g_qh + go);
            cp16(sb + SQL_OFF + so, g_ql + go);
        }
        CP_COMMIT();                                // group: Q
        cp_tile_kv(stg[0], base, moff, tid);
        CP_COMMIT();                                // group: tile 0
    }
    CP_WAIT(1);                                     // Q arrived
    __syncthreads();

    // Q fragments (fp16 hi/lo)
    uint32_t aH[4][4], aL[4][4];
    {
        int r = wid * 16 + (lane & 15);
        int ch = (lane >> 4) * 8;
        const __half* sQh = (const __half*)(smem + SQH_OFF);
        const __half* sQl = (const __half*)(smem + SQL_OFF);
#pragma unroll
        for (int ds = 0; ds < 4; ds++) {
            ldsm_x4(aH[ds], smem_u32(&sQh[r * ROWP_ + ds * 16 + ch]));
            ldsm_x4(aL[ds], smem_u32(&sQl[r * ROWP_ + ds * 16 + ch]));
        }
    }
    __syncthreads();    // stages 1,2 free
    cp_tile_kv(stg[1], base + KT_ * D_, moff + KT_, tid);
    CP_COMMIT();                                    // group: tile 1

    const uint32_t koff = (((lane & 7) + ((lane >> 4) << 3)) * ROWP_) * 2 + ((lane >> 3) & 1) * 16;
    const uint32_t voff = (lane & 15) * ROWP_ * 2 + (lane >> 4) * 16;
    const int rsb = ROWP_ * 2;
    const int qr0 = wid * 16 + (lane >> 2);

    // Per-row inverse rowsums (from rowsum_kernel)
    const float inv0 = g_inv[bh * S_ + qt * TQ_ + qr0];
    const float inv1 = g_inv[bh * S_ + qt * TQ_ + qr0 + 8];

    float o[8][4];
#pragma unroll
    for (int dn = 0; dn < 8; dn++)
#pragma unroll
        for (int c = 0; c < 4; c++) o[dn][c] = 0.f;

    int s = 0, sp2 = 2;
#pragma unroll 1
    for (int kt = 0; kt < NKT_; kt++) {
        CP_WAIT(1);
        __syncthreads();

        if (kt + 2 < NKT_)
            cp_tile_kv(stg[sp2], base + (size_t)(kt + 2) * KT_ * D_,
                       moff + (kt + 2) * KT_, tid);
        CP_COMMIT();

        const uint32_t bkf = stg[s] + KF_ + koff;
        const uint32_t bvv = stg[s] + VV_ + voff;
        const float* msk = (const float*)(smem + (s * STG_SZ + MSK_));

        // QK for chunk 0 (2-term fp16: qh*k -> c, ql*k -> e)
        float c0[4] = {0.f, 0.f, 0.f, 0.f}, c1[4] = {0.f, 0.f, 0.f, 0.f};
        float e0[4] = {0.f, 0.f, 0.f, 0.f}, e1[4] = {0.f, 0.f, 0.f, 0.f};
#pragma unroll
        for (int ds = 0; ds < 4; ds++) {
            uint32_t k4[4];
            ldsm_x4(k4, bkf + ds * 32);
            mma_f16(c0, aH[ds], k4);
            mma_f16(c1, aH[ds], k4 + 2);
            mma_f16(e0, aL[ds], k4);
            mma_f16(e1, aL[ds], k4 + 2);
        }

#pragma unroll
        for (int nc = 0; nc < 4; nc++) {
            const int n0 = nc * 16;
            // exp + normalize (final attn values)
            float pn[2][4];
            {
                int kc = n0 + ((lane & 3) << 1);
                float m00 = msk[kc] * inv0,     m01 = msk[kc + 1] * inv0;
                float m10 = msk[kc + 8] * inv0, m11 = msk[kc + 9] * inv0;
                float n00 = msk[kc] * inv1,     n01 = msk[kc + 1] * inv1;
                float n10 = msk[kc + 8] * inv1, n11 = msk[kc + 9] * inv1;
                pn[0][0] = m00 * __expf(c0[0] + e0[0]);
                pn[0][1] = m01 * __expf(c0[1] + e0[1]);
                pn[0][2] = n00 * __expf(c0[2] + e0[2]);
                pn[0][3] = n01 * __expf(c0[3] + e0[3]);
                pn[1][0] = m10 * __expf(c1[0] + e1[0]);
                pn[1][1] = m11 * __expf(c1[1] + e1[1]);
                pn[1][2] = n10 * __expf(c1[2] + e1[2]);
                pn[1][3] = n11 * __expf(c1[3] + e1[3]);
            }

            // QK for chunk nc+1 (covers exp latency)
            if (nc < 3) {
#pragma unroll
                for (int i = 0; i < 4; i++) { c0[i] = 0.f; c1[i] = 0.f; e0[i] = 0.f; e1[i] = 0.f; }
#pragma unroll
                for (int ds = 0; ds < 4; ds++) {
                    uint32_t k4[4];
                    ldsm_x4(k4, bkf + (n0 + 16) * rsb + ds * 32);
                    mma_f16(c0, aH[ds], k4);
                    mma_f16(c1, aH[ds], k4 + 2);
                    mma_f16(e0, aL[ds], k4);
                    mma_f16(e1, aL[ds], k4 + 2);
                }
            }

            // pack normalized p (fp16 2-split)
            uint32_t ph[4], pl[4];
            splitf16(pn[0][0], pn[0][1], ph[0], pl[0]);
            splitf16(pn[0][2], pn[0][3], ph[1], pl[1]);
            splitf16(pn[1][0], pn[1][1], ph[2], pl[2]);
            splitf16(pn[1][2], pn[1][3], ph[3], pl[3]);

            // PV
#pragma unroll
            for (int dp = 0; dp < 4; dp++) {
                uint32_t v4[4];
                ldsm_x4t(v4, bvv + n0 * rsb + dp * 32);
                mma_f16(o[2 * dp],     ph, v4);
                mma_f16(o[2 * dp],     pl, v4);
                mma_f16(o[2 * dp + 1], ph, v4 + 2);
                mma_f16(o[2 * dp + 1], pl, v4 + 2);
            }

            // Final attn store (streaming: never re-read)
#pragma unroll
            for (int nt = 0; nt < 2; nt++) {
                int col = kt * KT_ + n0 + nt * 8 + ((lane & 3) << 1);
                __stwt(reinterpret_cast<float2*>(Ag + (size_t)qr0 * S_ + col),
                       make_float2(pn[nt][0], pn[nt][1]));
                __stwt(reinterpret_cast<float2*>(Ag + (size_t)(qr0 + 8) * S_ + col),
                       make_float2(pn[nt][2], pn[nt][3]));
            }
        }

        sp2 = s;
        s = (s == 2) ? 0 : s + 1;
    }

    // out = o (p was already normalized before PV)
#pragma unroll
    for (int dn = 0; dn < 8; dn++) {
        int col = dn * 8 + ((lane & 3) << 1);
        *reinterpret_cast<float2*>(Og + (size_t)qr0 * D_ + col) =
            make_float2(o[dn][0], o[dn][1]);
        *reinterpret_cast<float2*>(Og + (size_t)(qr0 + 8) * D_ + col) =
            make_float2(o[dn][2], o[dn][3]);
    }
}

} // namespace

extern "C" void kernel_launch(void* const* d_in, const int* in_sizes, int n_in,
                              void* d_out, int out_size) {
    (void)in_sizes; (void)n_in; (void)out_size;
    const float* q = (const float*)d_in[0];
    const float* k = (const float*)d_in[1];
    const float* v = (const float*)d_in[2];
    const int*   m = (const int*)d_in[3];
    float* out = (float*)d_out;

    convert_kernel<<<2048, 256>>>(q, k, v, m);

    cudaFuncSetAttribute(rowsum_kernel, cudaFuncAttributeMaxDynamicSharedMemorySize, RSMEM_BYTES);
    dim3 grid(S_ / TQ_, BH_);
    rowsum_kernel<<<grid, THREADS_, RSMEM_BYTES>>>();

    cudaFuncSetAttribute(attn_kernel, cudaFuncAttributeMaxDynamicSharedMemorySize, SMEM_BYTES);
    attn_kernel<<<grid, THREADS_, SMEM_BYTES>>>(out);
}

// round 12
// speedup vs baseline: 2.5041x; 1.2498x over previous
#include <cuda_runtime.h>
#include <cuda_bf16.h>
#include <cuda_fp16.h>
#include <cstdint>

// ============================================================================
// Fused SDPA with attn-matrix output.
// R12: all-fp16 single-term tensor math.
//   QK: q(fp16) x k(fp16) -- identical in rowsum & attn kernels (rows of attn
//       sum to exactly 1). PV: p(fp16) x v(fp16). 16 mma/chunk (was 32).
//   convert_kernel: Q(/8),K,V -> fp16; mask -> float.
//   rowsum_kernel:  fp16 QK -> exp -> rowsum -> 1/rowsum.
//   attn_kernel:    fp16 QK -> p=mask*exp*inv (NORMALIZED, __stwt to attn)
//                   -> PV fp16 -> out written as-is.
// ============================================================================

namespace {

constexpr int S_  = 2048;
constexpr int D_  = 64;
constexpr int BH_ = 32;          // B*H
constexpr int TQ_ = 128;         // queries per CTA
constexpr int KT_ = 64;          // keys per stage
constexpr int NKT_ = S_ / KT_;   // 32 tiles
constexpr int THREADS_ = 256;    // 8 warps
constexpr int ROWP_ = 72;        // padded 16-bit row (144B) -> conflict-free LDSM
constexpr int NELEM_ = BH_ * S_ * D_;   // 4.19M per tensor

// ---- scratch ----
__device__ __half g_qf[NELEM_];                 // Q/8 fp16
__device__ __half g_kf[NELEM_];                 // K fp16
__device__ __half g_v[NELEM_];                  // V fp16
__device__ float g_mf[2 * S_];
__device__ float g_inv[BH_ * S_];               // 1/rowsum per (bh, row)

// ---- attn kernel smem (3 stages; Q overlays stage 1 in prologue) ----
constexpr int KF_  = 0;
constexpr int VV_  = KF_ + KT_ * ROWP_ * 2;          // 9216
constexpr int MSK_ = VV_ + KT_ * ROWP_ * 2;          // 18432 (within stage)
constexpr int STG_SZ = MSK_ + KT_ * 4;               // 18688
constexpr int SQ_OFF = STG_SZ;                       // Q fp16 (18432 <= STG_SZ)
constexpr int SMEM_BYTES = 3 * STG_SZ;               // 56064

// ---- rowsum kernel smem (separate Q region + 3 small stages) ----
constexpr int RQ_OFF = 0;                            // Q fp16: 18432
constexpr int RSTG_OFF = TQ_ * ROWP_ * 2;            // 18432
constexpr int RKF_ = 0;
constexpr int RMSK_ = KT_ * ROWP_ * 2;               // 9216 (within stage)
constexpr int RSTG_SZ = RMSK_ + KT_ * 4;             // 9472
constexpr int RSMEM_BYTES = RSTG_OFF + 3 * RSTG_SZ;  // 46848

__device__ __forceinline__ uint32_t smem_u32(const void* p) {
    return (uint32_t)__cvta_generic_to_shared(p);
}
__device__ __forceinline__ void cp16(uint32_t dst, const void* src) {
    asm volatile("cp.async.cg.shared.global [%0], [%1], 16;" :: "r"(dst), "l"(src));
}
#define CP_COMMIT() asm volatile("cp.async.commit_group;" ::: "memory")
#define CP_WAIT(n)  asm volatile("cp.async.wait_group %0;" :: "n"(n) : "memory")

__device__ __forceinline__ void ldsm_x4(uint32_t a[4], uint32_t addr) {
    asm volatile("ldmatrix.sync.aligned.m8n8.x4.shared.b16 {%0,%1,%2,%3}, [%4];"
                 : "=r"(a[0]), "=r"(a[1]), "=r"(a[2]), "=r"(a[3]) : "r"(addr));
}
__device__ __forceinline__ void ldsm_x4t(uint32_t a[4], uint32_t addr) {
    asm volatile("ldmatrix.sync.aligned.m8n8.x4.trans.shared.b16 {%0,%1,%2,%3}, [%4];"
                 : "=r"(a[0]), "=r"(a[1]), "=r"(a[2]), "=r"(a[3]) : "r"(addr));
}
__device__ __forceinline__ void mma_f16(float c[4], const uint32_t a[4], const uint32_t b[2]) {
    asm volatile(
        "mma.sync.aligned.m16n8k16.row.col.f32.f16.f16.f32 "
        "{%0,%1,%2,%3}, {%4,%5,%6,%7}, {%8,%9}, {%0,%1,%2,%3};"
        : "+f"(c[0]), "+f"(c[1]), "+f"(c[2]), "+f"(c[3])
        : "r"(a[0]), "r"(a[1]), "r"(a[2]), "r"(a[3]), "r"(b[0]), "r"(b[1]));
}
__device__ __forceinline__ uint2 pack_f16x4(float4 v) {
    __half2 a = __floats2half2_rn(v.x, v.y);
    __half2 b = __floats2half2_rn(v.z, v.w);
    return make_uint2(*reinterpret_cast<uint32_t*>(&a), *reinterpret_cast<uint32_t*>(&b));
}
__device__ __forceinline__ uint32_t h2_of(float x, float y) {
    __half2 h = __floats2half2_rn(x, y);
    return *reinterpret_cast<uint32_t*>(&h);
}

// ---------------------------------------------------------------------------
__global__ void __launch_bounds__(256)
convert_kernel(const float* __restrict__ q, const float* __restrict__ k,
               const float* __restrict__ v, const int* __restrict__ m) {
    const int N4 = NELEM_ / 4;
    const int stride = gridDim.x * blockDim.x;
    for (int j = blockIdx.x * blockDim.x + threadIdx.x; j < N4; j += stride) {
        float4 x = reinterpret_cast<const float4*>(q)[j];
        x.x *= 0.125f; x.y *= 0.125f; x.z *= 0.125f; x.w *= 0.125f;
        reinterpret_cast<uint2*>(g_qf)[j] = pack_f16x4(x);
        reinterpret_cast<uint2*>(g_kf)[j] = pack_f16x4(reinterpret_cast<const float4*>(k)[j]);
        reinterpret_cast<uint2*>(g_v)[j]  = pack_f16x4(reinterpret_cast<const float4*>(v)[j]);
    }
    for (int j = blockIdx.x * blockDim.x + threadIdx.x; j < 2 * S_; j += stride)
        g_mf[j] = m[j] ? 1.f : 0.f;
}

// ---------------------------------------------------------------------------
// rowsum_kernel: fp16 QK -> exp -> rowsum; writes 1/rowsum.
// ---------------------------------------------------------------------------
__device__ __forceinline__ void cp_tile_k16(uint32_t stg, size_t kvoff,
                                            size_t moff, int tid) {
#pragma unroll
    for (int i = 0; i < 2; i++) {
        int c = tid + THREADS_ * i;                 // 0..511 (64 rows x 8 chunks)
        int row = c >> 3, j = c & 7;
        cp16(stg + RKF_ + row * 144 + j * 16, g_kf + kvoff + row * 64 + j * 8);
    }
    if (tid < 16) cp16(stg + RMSK_ + tid * 16, g_mf + moff + tid * 4);
}

__global__ void __launch_bounds__(THREADS_, 3)
rowsum_kernel() {
    extern __shared__ char smem[];
    const uint32_t sb = smem_u32(smem);

    const int qt = blockIdx.x;
    const int bh = blockIdx.y;
    const int tid = threadIdx.x;
    const int wid = tid >> 5;
    const int lane = tid & 31;
    const int b = bh >> 4;

    const size_t base = (size_t)bh * S_ * D_;
    const size_t qoff = base + (size_t)qt * TQ_ * D_;
    const size_t moff = (size_t)b * S_;

    const uint32_t stg[3] = {sb + RSTG_OFF, sb + RSTG_OFF + RSTG_SZ,
                             sb + RSTG_OFF + 2 * RSTG_SZ};

    // Prologue: Q fp16 (1024 chunks) + tiles 0,1
    {
#pragma unroll
        for (int i = 0; i < 4; i++) {
            int c = tid + THREADS_ * i;             // 0..1023
            int row = c >> 3, j = c & 7;
            cp16(sb + RQ_OFF + row * 144 + j * 16, g_qf + qoff + row * 64 + j * 8);
        }
        cp_tile_k16(stg[0], base, moff, tid);
        CP_COMMIT();
        cp_tile_k16(stg[1], base + KT_ * D_, moff + KT_, tid);
        CP_COMMIT();
    }
    CP_WAIT(1);
    __syncthreads();

    // Q fragments
    uint32_t qf[4][4];
    {
        int r = wid * 16 + (lane & 15);
        int ch = (lane >> 4) * 8;
        const __half* sQ = (const __half*)(smem + RQ_OFF);
#pragma unroll
        for (int ds = 0; ds < 4; ds++)
            ldsm_x4(qf[ds], smem_u32(&sQ[r * ROWP_ + ds * 16 + ch]));
    }

    const uint32_t koff = (((lane & 7) + ((lane >> 4) << 3)) * ROWP_) * 2 + ((lane >> 3) & 1) * 16;
    const int rsb = ROWP_ * 2;
    float rs0 = 0.f, rs1 = 0.f;

    int s = 0, sp2 = 2;
#pragma unroll 1
    for (int kt = 0; kt < NKT_; kt++) {
        if (kt > 0) { CP_WAIT(1); __syncthreads(); }
        if (kt + 2 < NKT_)
            cp_tile_k16(stg[sp2], base + (size_t)(kt + 2) * KT_ * D_,
                        moff + (kt + 2) * KT_, tid);
        CP_COMMIT();

        const uint32_t bkf = stg[s] + RKF_ + koff;
        const float* msk = (const float*)(smem + RSTG_OFF + s * RSTG_SZ + RMSK_);

#pragma unroll
        for (int nc = 0; nc < 4; nc++) {
            const int n0 = nc * 16;
            float c0[4] = {0.f, 0.f, 0.f, 0.f};
            float c1[4] = {0.f, 0.f, 0.f, 0.f};
#pragma unroll
            for (int ds = 0; ds < 4; ds++) {
                uint32_t k4[4];
                ldsm_x4(k4, bkf + n0 * rsb + ds * 32);
                mma_f16(c0, qf[ds], k4);
                mma_f16(c1, qf[ds], k4 + 2);
            }
            int kc = n0 + ((lane & 3) << 1);
            float m00 = msk[kc],     m01 = msk[kc + 1];
            float m10 = msk[kc + 8], m11 = msk[kc + 9];
            rs0 += m00 * __expf(c0[0]) + m01 * __expf(c0[1])
                 + m10 * __expf(c1[0]) + m11 * __expf(c1[1]);
            rs1 += m00 * __expf(c0[2]) + m01 * __expf(c0[3])
                 + m10 * __expf(c1[2]) + m11 * __expf(c1[3]);
        }
        sp2 = s;
        s = (s == 2) ? 0 : s + 1;
    }

    rs0 += __shfl_xor_sync(0xffffffffu, rs0, 1);
    rs0 += __shfl_xor_sync(0xffffffffu, rs0, 2);
    rs1 += __shfl_xor_sync(0xffffffffu, rs1, 1);
    rs1 += __shfl_xor_sync(0xffffffffu, rs1, 2);
    if ((lane & 3) == 0) {
        int r = qt * TQ_ + wid * 16 + (lane >> 2);
        g_inv[bh * S_ + r]     = 1.f / rs0;
        g_inv[bh * S_ + r + 8] = 1.f / rs1;
    }
}

// ---------------------------------------------------------------------------
// Main attention kernel: writes NORMALIZED attn directly (no sweep).
// ---------------------------------------------------------------------------
__device__ __forceinline__ void cp_tile_kv(uint32_t stg, size_t kvoff,
                                           size_t moff, int tid) {
#pragma unroll
    for (int i = 0; i < 2; i++) {
        int c = tid + THREADS_ * i;                 // 0..511
        int row = c >> 3, j = c & 7;
        uint32_t so = row * 144 + j * 16;
        size_t go = kvoff + row * 64 + j * 8;
        cp16(stg + KF_ + so, g_kf + go);
        cp16(stg + VV_ + so, g_v + go);
    }
    if (tid < 16) cp16(stg + MSK_ + tid * 16, g_mf + moff + tid * 4);
}

__global__ void __launch_bounds__(THREADS_, 2)
attn_kernel(float* __restrict__ Out) {
    extern __shared__ char smem[];
    const uint32_t sb = smem_u32(smem);

    const int qt = blockIdx.x;
    const int bh = blockIdx.y;
    const int tid = threadIdx.x;
    const int wid = tid >> 5;
    const int lane = tid & 31;
    const int b = bh >> 4;

    const size_t base = (size_t)bh * S_ * D_;
    const size_t qoff = base + (size_t)qt * TQ_ * D_;
    const size_t moff = (size_t)b * S_;
    float* Og = Out + qoff;
    float* Ag = Out + (size_t)BH_ * S_ * D_ + (size_t)bh * S_ * S_ + (size_t)qt * TQ_ * S_;

    const uint32_t stg[3] = {sb, sb + STG_SZ, sb + 2 * STG_SZ};

    // Prologue: Q (overlaying stage 1), tile 0
    {
#pragma unroll
        for (int i = 0; i < 4; i++) {
            int c = tid + THREADS_ * i;             // 0..1023
            int row = c >> 3, j = c & 7;
            cp16(sb + SQ_OFF + row * 144 + j * 16, g_qf + qoff + row * 64 + j * 8);
        }
        CP_COMMIT();                                // group: Q
        cp_tile_kv(stg[0], base, moff, tid);
        CP_COMMIT();                                // group: tile 0
    }
    CP_WAIT(1);                                     // Q arrived
    __syncthreads();

    // Q fragments (fp16)
    uint32_t aH[4][4];
    {
        int r = wid * 16 + (lane & 15);
        int ch = (lane >> 4) * 8;
        const __half* sQ = (const __half*)(smem + SQ_OFF);
#pragma unroll
        for (int ds = 0; ds < 4; ds++)
            ldsm_x4(aH[ds], smem_u32(&sQ[r * ROWP_ + ds * 16 + ch]));
    }
    __syncthreads();    // stage 1 free
    cp_tile_kv(stg[1], base + KT_ * D_, moff + KT_, tid);
    CP_COMMIT();                                    // group: tile 1

    const uint32_t koff = (((lane & 7) + ((lane >> 4) << 3)) * ROWP_) * 2 + ((lane >> 3) & 1) * 16;
    const uint32_t voff = (lane & 15) * ROWP_ * 2 + (lane >> 4) * 16;
    const int rsb = ROWP_ * 2;
    const int qr0 = wid * 16 + (lane >> 2);

    // Per-row inverse rowsums (from rowsum_kernel; same fp16 QK -> exact rows)
    const float inv0 = g_inv[bh * S_ + qt * TQ_ + qr0];
    const float inv1 = g_inv[bh * S_ + qt * TQ_ + qr0 + 8];

    float o[8][4];
#pragma unroll
    for (int dn = 0; dn < 8; dn++)
#pragma unroll
        for (int c = 0; c < 4; c++) o[dn][c] = 0.f;

    int s = 0, sp2 = 2;
#pragma unroll 1
    for (int kt = 0; kt < NKT_; kt++) {
        CP_WAIT(1);
        __syncthreads();

        if (kt + 2 < NKT_)
            cp_tile_kv(stg[sp2], base + (size_t)(kt + 2) * KT_ * D_,
                       moff + (kt + 2) * KT_, tid);
        CP_COMMIT();

        const uint32_t bkf = stg[s] + KF_ + koff;
        const uint32_t bvv = stg[s] + VV_ + voff;
        const float* msk = (const float*)(smem + (s * STG_SZ + MSK_));

        // QK for chunk 0 (single-term fp16)
        float c0[4] = {0.f, 0.f, 0.f, 0.f}, c1[4] = {0.f, 0.f, 0.f, 0.f};
#pragma unroll
        for (int ds = 0; ds < 4; ds++) {
            uint32_t k4[4];
            ldsm_x4(k4, bkf + ds * 32);
            mma_f16(c0, aH[ds], k4);
            mma_f16(c1, aH[ds], k4 + 2);
        }

#pragma unroll
        for (int nc = 0; nc < 4; nc++) {
            const int n0 = nc * 16;
            // exp + normalize (final attn values)
            float pn[2][4];
            {
                int kc = n0 + ((lane & 3) << 1);
                float m00 = msk[kc] * inv0,     m01 = msk[kc + 1] * inv0;
                float m10 = msk[kc + 8] * inv0, m11 = msk[kc + 9] * inv0;
                float n00 = msk[kc] * inv1,     n01 = msk[kc + 1] * inv1;
                float n10 = msk[kc + 8] * inv1, n11 = msk[kc + 9] * inv1;
                pn[0][0] = m00 * __expf(c0[0]);
                pn[0][1] = m01 * __expf(c0[1]);
                pn[0][2] = n00 * __expf(c0[2]);
                pn[0][3] = n01 * __expf(c0[3]);
                pn[1][0] = m10 * __expf(c1[0]);
                pn[1][1] = m11 * __expf(c1[1]);
                pn[1][2] = n10 * __expf(c1[2]);
                pn[1][3] = n11 * __expf(c1[3]);
            }

            // QK for chunk nc+1 (covers exp latency)
            if (nc < 3) {
#pragma unroll
                for (int i = 0; i < 4; i++) { c0[i] = 0.f; c1[i] = 0.f; }
#pragma unroll
                for (int ds = 0; ds < 4; ds++) {
                    uint32_t k4[4];
                    ldsm_x4(k4, bkf + (n0 + 16) * rsb + ds * 32);
                    mma_f16(c0, aH[ds], k4);
                    mma_f16(c1, aH[ds], k4 + 2);
                }
            }

            // pack normalized p (single fp16)
            uint32_t ph[4];
            ph[0] = h2_of(pn[0][0], pn[0][1]);
            ph[1] = h2_of(pn[0][2], pn[0][3]);
            ph[2] = h2_of(pn[1][0], pn[1][1]);
            ph[3] = h2_of(pn[1][2], pn[1][3]);

            // PV (single-term fp16)
#pragma unroll
            for (int dp = 0; dp < 4; dp++) {
                uint32_t v4[4];
                ldsm_x4t(v4, bvv + n0 * rsb + dp * 32);
                mma_f16(o[2 * dp],     ph, v4);
                mma_f16(o[2 * dp + 1], ph, v4 + 2);
            }

            // Final attn store (streaming: never re-read)
#pragma unroll
            for (int nt = 0; nt < 2; nt++) {
                int col = kt * KT_ + n0 + nt * 8 + ((lane & 3) << 1);
                __stwt(reinterpret_cast<float2*>(Ag + (size_t)qr0 * S_ + col),
                       make_float2(pn[nt][0], pn[nt][1]));
                __stwt(reinterpret_cast<float2*>(Ag + (size_t)(qr0 + 8) * S_ + col),
                       make_float2(pn[nt][2], pn[nt][3]));
            }
        }

        sp2 = s;
        s = (s == 2) ? 0 : s + 1;
    }

    // out = o (p was already normalized before PV)
#pragma unroll
    for (int dn = 0; dn < 8; dn++) {
        int col = dn * 8 + ((lane & 3) << 1);
        *reinterpret_cast<float2*>(Og + (size_t)qr0 * D_ + col) =
            make_float2(o[dn][0], o[dn][1]);
        *reinterpret_cast<float2*>(Og + (size_t)(qr0 + 8) * D_ + col) =
            make_float2(o[dn][2], o[dn][3]);
    }
}

} // namespace

extern "C" void kernel_launch(void* const* d_in, const int* in_sizes, int n_in,
                              void* d_out, int out_size) {
    (void)in_sizes; (void)n_in; (void)out_size;
    const float* q = (const float*)d_in[0];
    const float* k = (const float*)d_in[1];
    const float* v = (const float*)d_in[2];
    const int*   m = (const int*)d_in[3];
    float* out = (float*)d_out;

    convert_kernel<<<2048, 256>>>(q, k, v, m);

    cudaFuncSetAttribute(rowsum_kernel, cudaFuncAttributeMaxDynamicSharedMemorySize, RSMEM_BYTES);
    dim3 grid(S_ / TQ_, BH_);
    rowsum_kernel<<<grid, THREADS_, RSMEM_BYTES>>>();

    cudaFuncSetAttribute(attn_kernel, cudaFuncAttributeMaxDynamicSharedMemorySize, SMEM_BYTES);
    attn_kernel<<<grid, THREADS_, SMEM_BYTES>>>(out);
}